// round 5
// baseline (speedup 1.0000x reference)
#include <cuda_runtime.h>

// Problem constants
#define Nn   10000
#define Bb   4
#define Ff   16
#define Tt   12
#define Ee   160000
#define Cc   64
#define ROW  768          // Bb*Tt*Ff floats per node
#define ROW4 192          // ROW/4 (float4)

typedef unsigned long long u64;

__device__ __forceinline__ u64 ffma2(u64 a, u64 b, u64 c) {
    u64 d;
    asm("fma.rn.f32x2 %0, %1, %2, %3;" : "=l"(d) : "l"(a), "l"(b), "l"(c));
    return d;
}
__device__ __forceinline__ float hsum2(u64 v) {
    float lo, hi;
    asm("mov.b64 {%0, %1}, %2;" : "=f"(lo), "=f"(hi) : "l"(v));
    return lo + hi;
}
#define GROUP_BAR(gid) asm volatile("bar.sync %0, 64;" :: "r"((gid) + 1) : "memory")

// ---------------- scratch (device globals; no allocation) ----------------
__device__ float g_Tx0[Nn * ROW];
__device__ float g_Tx1[Nn * ROW];
__device__ float g_Tx2[Nn * ROW];
__device__ float g_deg[Nn];
__device__ int   g_degin[Nn];
__device__ int   g_off[Nn + 1];
__device__ int   g_cur[Nn];
__device__ int   g_srcs[Ee];

// ---------------- graph preprocessing ----------------
__global__ void k_zero() {
    int i = blockIdx.x * blockDim.x + threadIdx.x;
    if (i < Nn) { g_deg[i] = 0.0f; g_degin[i] = 0; }
}

__global__ void k_count(const int* __restrict__ ei) {
    int e = blockIdx.x * blockDim.x + threadIdx.x;
    if (e < Ee) {
        atomicAdd(&g_deg[ei[e]], 1.0f);       // out-degree by row
        atomicAdd(&g_degin[ei[Ee + e]], 1);   // in-degree by col
    }
}

// single-block exclusive scan over g_degin -> g_off, g_cur
__global__ void k_scan() {
    __shared__ int part[1024];
    int t = threadIdx.x;
    const int CH = 10;                 // 1024*10 >= Nn
    int base = t * CH;
    int local[CH];
    int s = 0;
#pragma unroll
    for (int i = 0; i < CH; i++) {
        int idx = base + i;
        int v = (idx < Nn) ? g_degin[idx] : 0;
        local[i] = v; s += v;
    }
    part[t] = s;
    __syncthreads();
    for (int off = 1; off < 1024; off <<= 1) {
        int v = (t >= off) ? part[t - off] : 0;
        __syncthreads();
        part[t] += v;
        __syncthreads();
    }
    int pre = (t == 0) ? 0 : part[t - 1];
#pragma unroll
    for (int i = 0; i < CH; i++) {
        int idx = base + i;
        if (idx < Nn) { g_off[idx] = pre; g_cur[idx] = pre; pre += local[i]; }
    }
    if (t == 1023) g_off[Nn] = part[1023];
}

__global__ void k_fill(const int* __restrict__ ei) {
    int e = blockIdx.x * blockDim.x + threadIdx.x;
    if (e < Ee) {
        int c = ei[Ee + e];
        int p = atomicAdd(&g_cur[c], 1);
        g_srcs[p] = ei[e];
    }
}

// ---------------- transpose x (B,N,F,T) -> Tx0 (N,B,T,F) ----------------
__global__ void k_transpose(const float* __restrict__ x) {
    int bn = blockIdx.x;               // b*Nn + n
    int b = bn / Nn, n = bn - b * Nn;
    __shared__ float tile[ROW4];
    int tid = threadIdx.x;             // 0..191
    tile[tid] = x[bn * ROW4 + tid];    // (f*12 + t)
    __syncthreads();
    int t = tid >> 4, f = tid & 15;
    g_Tx0[n * ROW + b * ROW4 + tid] = tile[f * Tt + t];  // (t*16 + f)
}

// ---------------- Lhat via CSR gather ----------------
__global__ void k_lhat1(const float* __restrict__ lamp) {
    int n = blockIdx.x, j = threadIdx.x;     // j: float4 index 0..191
    const float4* u = (const float4*)g_Tx0;
    float4 acc = make_float4(0.f, 0.f, 0.f, 0.f);
    int e = g_off[n], e1 = g_off[n + 1];
    for (; e + 4 <= e1; e += 4) {
        int s0 = g_srcs[e], s1 = g_srcs[e + 1], s2 = g_srcs[e + 2], s3 = g_srcs[e + 3];
        float4 v0 = u[s0 * ROW4 + j], v1 = u[s1 * ROW4 + j];
        float4 v2 = u[s2 * ROW4 + j], v3 = u[s3 * ROW4 + j];
        acc.x += (v0.x + v1.x) + (v2.x + v3.x);
        acc.y += (v0.y + v1.y) + (v2.y + v3.y);
        acc.z += (v0.z + v1.z) + (v2.z + v3.z);
        acc.w += (v0.w + v1.w) + (v2.w + v3.w);
    }
    for (; e < e1; e++) {
        float4 v = u[g_srcs[e] * ROW4 + j];
        acc.x += v.x; acc.y += v.y; acc.z += v.z; acc.w += v.w;
    }
    float4 un = u[n * ROW4 + j];
    float c2 = 2.0f / lamp[0];
    float dn = g_deg[n];
    float4 r;
    r.x = c2 * (dn * un.x - acc.x) - un.x;
    r.y = c2 * (dn * un.y - acc.y) - un.y;
    r.z = c2 * (dn * un.z - acc.z) - un.z;
    r.w = c2 * (dn * un.w - acc.w) - un.w;
    ((float4*)g_Tx1)[n * ROW4 + j] = r;
}

__global__ void k_lhat2(const float* __restrict__ lamp) {
    int n = blockIdx.x, j = threadIdx.x;
    const float4* u = (const float4*)g_Tx1;
    float4 acc = make_float4(0.f, 0.f, 0.f, 0.f);
    int e = g_off[n], e1 = g_off[n + 1];
    for (; e + 4 <= e1; e += 4) {
        int s0 = g_srcs[e], s1 = g_srcs[e + 1], s2 = g_srcs[e + 2], s3 = g_srcs[e + 3];
        float4 v0 = u[s0 * ROW4 + j], v1 = u[s1 * ROW4 + j];
        float4 v2 = u[s2 * ROW4 + j], v3 = u[s3 * ROW4 + j];
        acc.x += (v0.x + v1.x) + (v2.x + v3.x);
        acc.y += (v0.y + v1.y) + (v2.y + v3.y);
        acc.z += (v0.z + v1.z) + (v2.z + v3.z);
        acc.w += (v0.w + v1.w) + (v2.w + v3.w);
    }
    for (; e < e1; e++) {
        float4 v = u[g_srcs[e] * ROW4 + j];
        acc.x += v.x; acc.y += v.y; acc.z += v.z; acc.w += v.w;
    }
    float4 un = u[n * ROW4 + j];
    float4 t0 = ((const float4*)g_Tx0)[n * ROW4 + j];
    float c2 = 2.0f / lamp[0];
    float dn = g_deg[n];
    float4 r;
    r.x = 2.0f * (c2 * (dn * un.x - acc.x) - un.x) - t0.x;
    r.y = 2.0f * (c2 * (dn * un.y - acc.y) - un.y) - t0.y;
    r.z = 2.0f * (c2 * (dn * un.z - acc.z) - un.z) - t0.z;
    r.w = 2.0f * (c2 * (dn * un.w - acc.w) - un.w) - t0.w;
    ((float4*)g_Tx2)[n * ROW4 + j] = r;
}

// ---------------- fused cheb-proj + temporal conv + residual + LN ----------------
// f32x2-packed. ONE block of 768 threads per SM = 12 independent 64-thread
// groups free-running on named barriers (ids 1..12): 24 warps/SM for latency
// hiding, weights staged once per SM.
#define NG 12
#define GB_BASE 16640
#define GB_STRIDE 2456
#define SMEM_FLOATS (GB_BASE + NG * GB_STRIDE)   // 46112 floats = 184448 B
#define NTILE (Nn * Bb)

__global__ void __launch_bounds__(768, 1)
k_fused(const float* __restrict__ x,
        const float* __restrict__ chebW, const float* __restrict__ chebB,
        const float* __restrict__ timeW, const float* __restrict__ timeB,
        const float* __restrict__ resW,  const float* __restrict__ resB,
        const float* __restrict__ gamma, const float* __restrict__ beta,
        float* __restrict__ out)
{
    extern __shared__ float sm[];
    float* cb  = sm + 16384;
    float* trb = sm + 16448;
    float* gma = sm + 16512;
    float* bta = sm + 16576;

    const u64* wchu = (const u64*)(sm);          // [jp*64 + c]
    const u64* wtu  = (const u64*)(sm + 3072);   // [d*2048 + cip*64 + c]
    const u64* wru  = (const u64*)(sm + 15360);  // [fp*64 + c]

    int tid = threadIdx.x;

    // --- one-time weight staging (packed float2 over reduction pairs) ---
    for (int i = tid; i < 1536; i += 768) {          // cheb: jp(24), c(64)
        int jp = i >> 6, c = i & 63;
        sm[2 * i]     = chebW[(2 * jp) * 64 + c];
        sm[2 * i + 1] = chebW[(2 * jp + 1) * 64 + c];
    }
    for (int i = tid; i < 6144; i += 768) {          // time: d(3), cip(32), c(64)
        int d = i >> 11; int r = i & 2047;
        int cip = r >> 6; int c = r & 63;
        sm[3072 + 2 * i]     = timeW[c * 192 + (2 * cip) * 3 + d];
        sm[3072 + 2 * i + 1] = timeW[c * 192 + (2 * cip + 1) * 3 + d];
    }
    for (int i = tid; i < 512; i += 768) {           // res: fp(8), c(64)
        int fp = i >> 6, c = i & 63;
        sm[15360 + 2 * i]     = resW[c * 16 + 2 * fp];
        sm[15360 + 2 * i + 1] = resW[c * 16 + 2 * fp + 1];
    }
    if (tid < 64) {
        cb[tid]  = chebB[tid];
        trb[tid] = timeB[tid] + resB[tid];
        gma[tid] = gamma[tid];
        bta[tid] = beta[tid];
    }

    const int g = tid >> 6;        // group 0..11
    const int c = tid & 63;        // channel (also lane-in-group)
    const int lane = tid & 31;
    const int w01 = (tid >> 5) & 1;

    float* gbase  = sm + GB_BASE + g * GB_STRIDE;
    float* mytx   = gbase;              // 576: u64[jp(24)][t(12)]
    float* myspad = gbase + 576;        // 896: u64[cip(32)][tpos(14)]
    float* myxr   = gbase + 1472;       // 192: u64[fp(8)][t(12)]
    float* myhs   = gbase + 1664;       // 768: [t(12)][c(64)]
    float* mymu   = gbase + 2432;
    float* myrs   = gbase + 2444;

    // zero spad boundary slots (tpos 0 and 13) once; only [1..12] rewritten
    {
        float* sp = myspad + (c >> 1) * 28 + (c & 1);
        sp[0] = 0.f; sp[26] = 0.f;
    }
    __syncthreads();   // weights + boundary visible to all groups

    for (int tile = blockIdx.x * NG + g; tile < NTILE; tile += gridDim.x * NG) {
        const int n = tile >> 2;       // node
        const int b = tile & 3;        // batch

        // ---- Stage 0: group-local loads (coalesced global -> interleaved smem) ----
        {
            const float* srcs[3] = { g_Tx0, g_Tx1, g_Tx2 };
#pragma unroll
            for (int kk = 0; kk < 3; kk++) {
                const float* src = srcs[kk] + n * ROW + b * ROW4;
#pragma unroll
                for (int rep = 0; rep < 3; rep++) {
                    int rr = rep * 64 + c;          // 0..191 = t*16+f
                    int t = rr >> 4, f = rr & 15;
                    int j = kk * 16 + f;
                    mytx[(j >> 1) * 24 + t * 2 + (j & 1)] = src[rr];
                }
            }
            const float* xs = x + (b * Nn + n) * ROW4;
#pragma unroll
            for (int rep = 0; rep < 3; rep++) {
                int rr = rep * 64 + c;              // 0..191 = f*12+t
                int f = rr / 12, t = rr - f * 12;
                myxr[(f >> 1) * 24 + t * 2 + (f & 1)] = xs[rr];
            }
        }
        GROUP_BAR(g);

        // ---- Stage A: cheb projection (packed over j-pairs), relu -> spad ----
        {
            u64 acc[12];
#pragma unroll
            for (int t = 0; t < 12; t++) acc[t] = 0ull;
#pragma unroll 2
            for (int jp = 0; jp < 24; jp++) {
                const ulonglong2* row = (const ulonglong2*)(mytx + jp * 24);
                ulonglong2 p0 = row[0], p1 = row[1], p2 = row[2];
                ulonglong2 p3 = row[3], p4 = row[4], p5 = row[5];
                u64 w = wchu[jp * 64 + c];
                acc[0]  = ffma2(p0.x, w, acc[0]);  acc[1]  = ffma2(p0.y, w, acc[1]);
                acc[2]  = ffma2(p1.x, w, acc[2]);  acc[3]  = ffma2(p1.y, w, acc[3]);
                acc[4]  = ffma2(p2.x, w, acc[4]);  acc[5]  = ffma2(p2.y, w, acc[5]);
                acc[6]  = ffma2(p3.x, w, acc[6]);  acc[7]  = ffma2(p3.y, w, acc[7]);
                acc[8]  = ffma2(p4.x, w, acc[8]);  acc[9]  = ffma2(p4.y, w, acc[9]);
                acc[10] = ffma2(p5.x, w, acc[10]); acc[11] = ffma2(p5.y, w, acc[11]);
            }
            float bias = cb[c];
            float* sp = myspad + (c >> 1) * 28 + (c & 1);
#pragma unroll
            for (int t = 0; t < 12; t++)
                sp[(t + 1) * 2] = fmaxf(hsum2(acc[t]) + bias, 0.f);
        }
        GROUP_BAR(g);

        // ---- Stage B: temporal conv + residual in two 6-t half-passes ----
        float h[12];
        {
            float bb = trb[c];
#pragma unroll
            for (int half = 0; half < 2; half++) {
                u64 acc[6];
#pragma unroll
                for (int tt = 0; tt < 6; tt++) acc[tt] = 0ull;
#pragma unroll 1
                for (int cip = 0; cip < 32; cip++) {
                    const ulonglong2* row =
                        (const ulonglong2*)(myspad + cip * 28 + 12 * half);
                    ulonglong2 q0 = row[0], q1 = row[1], q2 = row[2], q3 = row[3];
                    u64 w0 = wtu[cip * 64 + c];
                    u64 w1 = wtu[2048 + cip * 64 + c];
                    u64 w2 = wtu[4096 + cip * 64 + c];
                    acc[0] = ffma2(q0.x, w0, acc[0]);
                    acc[0] = ffma2(q0.y, w1, acc[0]);
                    acc[0] = ffma2(q1.x, w2, acc[0]);
                    acc[1] = ffma2(q0.y, w0, acc[1]);
                    acc[1] = ffma2(q1.x, w1, acc[1]);
                    acc[1] = ffma2(q1.y, w2, acc[1]);
                    acc[2] = ffma2(q1.x, w0, acc[2]);
                    acc[2] = ffma2(q1.y, w1, acc[2]);
                    acc[2] = ffma2(q2.x, w2, acc[2]);
                    acc[3] = ffma2(q1.y, w0, acc[3]);
                    acc[3] = ffma2(q2.x, w1, acc[3]);
                    acc[3] = ffma2(q2.y, w2, acc[3]);
                    acc[4] = ffma2(q2.x, w0, acc[4]);
                    acc[4] = ffma2(q2.y, w1, acc[4]);
                    acc[4] = ffma2(q3.x, w2, acc[4]);
                    acc[5] = ffma2(q2.y, w0, acc[5]);
                    acc[5] = ffma2(q3.x, w1, acc[5]);
                    acc[5] = ffma2(q3.y, w2, acc[5]);
                }
#pragma unroll 2
                for (int fp = 0; fp < 8; fp++) {
                    const ulonglong2* row =
                        (const ulonglong2*)(myxr + fp * 24 + 12 * half);
                    ulonglong2 p0 = row[0], p1 = row[1], p2 = row[2];
                    u64 w = wru[fp * 64 + c];
                    acc[0] = ffma2(p0.x, w, acc[0]);
                    acc[1] = ffma2(p0.y, w, acc[1]);
                    acc[2] = ffma2(p1.x, w, acc[2]);
                    acc[3] = ffma2(p1.y, w, acc[3]);
                    acc[4] = ffma2(p2.x, w, acc[4]);
                    acc[5] = ffma2(p2.y, w, acc[5]);
                }
#pragma unroll
                for (int tt = 0; tt < 6; tt++) {
                    int t = half * 6 + tt;
                    h[t] = fmaxf(hsum2(acc[tt]) + bb, 0.f);
                    myhs[t * 64 + c] = h[t];
                }
            }
        }
        GROUP_BAR(g);

        // ---- LN stats: each of the group's 2 warps reduces 6 t-rows ----
        {
#pragma unroll
            for (int r = 0; r < 6; r++) {
                int t = w01 * 6 + r;
                float v1 = myhs[t * 64 + lane];
                float v2 = myhs[t * 64 + 32 + lane];
                float s = v1 + v2;
                float sq = v1 * v1 + v2 * v2;
#pragma unroll
                for (int o = 16; o > 0; o >>= 1) {
                    s  += __shfl_xor_sync(0xffffffffu, s, o);
                    sq += __shfl_xor_sync(0xffffffffu, sq, o);
                }
                if (lane == 0) {
                    float mu = s * (1.0f / 64.0f);
                    float var = sq * (1.0f / 64.0f) - mu * mu;
                    mymu[t] = mu;
                    myrs[t] = rsqrtf(var + 1e-5f);
                }
            }
        }
        GROUP_BAR(g);

        // ---- normalize + write out (B,N,C,T), coalesced float4 ----
        // (no trailing barrier: next stage-0 writes only tx/xr, whose last
        //  readers are behind the stage-A/B barriers above)
        {
            float ga = gma[c], be = bta[c];
            float o[12];
#pragma unroll
            for (int t = 0; t < 12; t++)
                o[t] = (h[t] - mymu[t]) * myrs[t] * ga + be;
            float* op = out + (((size_t)b * Nn + n) * 64 + c) * 12;
            float4* op4 = (float4*)op;
            op4[0] = make_float4(o[0], o[1], o[2],  o[3]);
            op4[1] = make_float4(o[4], o[5], o[6],  o[7]);
            op4[2] = make_float4(o[8], o[9], o[10], o[11]);
        }
    }
}

// ---------------- launcher ----------------
extern "C" void kernel_launch(void* const* d_in, const int* in_sizes, int n_in,
                              void* d_out, int out_size)
{
    const float* x     = (const float*)d_in[0];
    const int*   ei    = (const int*)d_in[1];
    const float* lam   = (const float*)d_in[2];
    const float* chebW = (const float*)d_in[3];
    const float* chebB = (const float*)d_in[4];
    const float* timeW = (const float*)d_in[5];
    const float* timeB = (const float*)d_in[6];
    const float* resW  = (const float*)d_in[7];
    const float* resB  = (const float*)d_in[8];
    const float* gma   = (const float*)d_in[9];
    const float* bta   = (const float*)d_in[10];
    float* out = (float*)d_out;

    k_zero<<<(Nn + 255) / 256, 256>>>();
    k_count<<<(Ee + 255) / 256, 256>>>(ei);
    k_scan<<<1, 1024>>>();
    k_fill<<<(Ee + 255) / 256, 256>>>(ei);
    k_transpose<<<Bb * Nn, 192>>>(x);
    k_lhat1<<<Nn, 192>>>(lam);
    k_lhat2<<<Nn, 192>>>(lam);

    cudaFuncSetAttribute(k_fused, cudaFuncAttributeMaxDynamicSharedMemorySize,
                         SMEM_FLOATS * 4);
    // one 768-thread block per SM: 12 free-running groups, 24 warps/SM
    k_fused<<<148, 768, SMEM_FLOATS * 4>>>(x, chebW, chebB, timeW, timeB,
                                           resW, resB, gma, bta, out);
}

// round 6
// speedup vs baseline: 1.0970x; 1.0970x over previous
#include <cuda_runtime.h>
#include <cuda_bf16.h>
#include <cstdint>

// Problem constants
#define Nn   10000
#define Bb   4
#define Ff   16
#define Tt   12
#define Ee   160000
#define Cc   64
#define ROW  768          // Bb*Tt*Ff floats per node (4 segments of 192)
#define SEG  192          // floats per (n,b) row
#define SEG4 48           // float4 per (n,b) row

typedef unsigned long long u64;
typedef __nv_bfloat16 bf16;

__device__ __forceinline__ u64 ffma2(u64 a, u64 b, u64 c) {
    u64 d;
    asm("fma.rn.f32x2 %0, %1, %2, %3;" : "=l"(d) : "l"(a), "l"(b), "l"(c));
    return d;
}
__device__ __forceinline__ float hsum2(u64 v) {
    float lo, hi;
    asm("mov.b64 {%0, %1}, %2;" : "=f"(lo), "=f"(hi) : "l"(v));
    return lo + hi;
}
#define GROUP_BAR(gid) asm volatile("bar.sync %0, 64;" :: "r"((gid) + 1) : "memory")

__device__ __forceinline__ void mma_bf16(float c[4], const uint32_t a[4],
                                         uint32_t b0, uint32_t b1) {
    asm volatile(
        "mma.sync.aligned.m16n8k16.row.col.f32.bf16.bf16.f32 "
        "{%0,%1,%2,%3}, {%4,%5,%6,%7}, {%8,%9}, {%0,%1,%2,%3};"
        : "+f"(c[0]), "+f"(c[1]), "+f"(c[2]), "+f"(c[3])
        : "r"(a[0]), "r"(a[1]), "r"(a[2]), "r"(a[3]), "r"(b0), "r"(b1));
}

// ---------------- scratch (device globals; no allocation) ----------------
__device__ float g_Tx1[Nn * ROW];
__device__ float g_Tx2[Nn * ROW];
__device__ float g_deg[Nn];
__device__ int   g_degin[Nn];
__device__ int   g_off[Nn + 1];
__device__ int   g_cur[Nn];
__device__ int   g_srcs[Ee];

// ---------------- graph preprocessing ----------------
__global__ void k_zero() {
    int i = blockIdx.x * blockDim.x + threadIdx.x;
    if (i < Nn) { g_deg[i] = 0.0f; g_degin[i] = 0; }
}

__global__ void k_count(const int* __restrict__ ei) {
    int e = blockIdx.x * blockDim.x + threadIdx.x;
    if (e < Ee) {
        atomicAdd(&g_deg[ei[e]], 1.0f);       // out-degree by row
        atomicAdd(&g_degin[ei[Ee + e]], 1);   // in-degree by col
    }
}

__global__ void k_scan() {
    __shared__ int part[1024];
    int t = threadIdx.x;
    const int CH = 10;
    int base = t * CH;
    int local[CH];
    int s = 0;
#pragma unroll
    for (int i = 0; i < CH; i++) {
        int idx = base + i;
        int v = (idx < Nn) ? g_degin[idx] : 0;
        local[i] = v; s += v;
    }
    part[t] = s;
    __syncthreads();
    for (int off = 1; off < 1024; off <<= 1) {
        int v = (t >= off) ? part[t - off] : 0;
        __syncthreads();
        part[t] += v;
        __syncthreads();
    }
    int pre = (t == 0) ? 0 : part[t - 1];
#pragma unroll
    for (int i = 0; i < CH; i++) {
        int idx = base + i;
        if (idx < Nn) { g_off[idx] = pre; g_cur[idx] = pre; pre += local[i]; }
    }
    if (t == 1023) g_off[Nn] = part[1023];
}

__global__ void k_fill(const int* __restrict__ ei) {
    int e = blockIdx.x * blockDim.x + threadIdx.x;
    if (e < Ee) {
        int c = ei[Ee + e];
        int p = atomicAdd(&g_cur[c], 1);
        g_srcs[p] = ei[e];
    }
}

// ---------------- Lhat via CSR gather, in x's native (b,n,f,t) layout ----------------
// Tx1 = (2/lam)*(deg*x - agg(x)) - x
__global__ void k_lhat1(const float* __restrict__ x, const float* __restrict__ lamp) {
    int n = blockIdx.x, j = threadIdx.x;     // j 0..191: b = j/48, r4 = j%48
    int b = j / SEG4, r4 = j - b * SEG4;
    int boff = b * Nn;
    const float4* u = (const float4*)x;
    float4 acc = make_float4(0.f, 0.f, 0.f, 0.f);
    int e = g_off[n], e1 = g_off[n + 1];
    for (; e + 4 <= e1; e += 4) {
        int s0 = g_srcs[e], s1 = g_srcs[e + 1], s2 = g_srcs[e + 2], s3 = g_srcs[e + 3];
        float4 v0 = u[(boff + s0) * SEG4 + r4], v1 = u[(boff + s1) * SEG4 + r4];
        float4 v2 = u[(boff + s2) * SEG4 + r4], v3 = u[(boff + s3) * SEG4 + r4];
        acc.x += (v0.x + v1.x) + (v2.x + v3.x);
        acc.y += (v0.y + v1.y) + (v2.y + v3.y);
        acc.z += (v0.z + v1.z) + (v2.z + v3.z);
        acc.w += (v0.w + v1.w) + (v2.w + v3.w);
    }
    for (; e < e1; e++) {
        float4 v = u[(boff + g_srcs[e]) * SEG4 + r4];
        acc.x += v.x; acc.y += v.y; acc.z += v.z; acc.w += v.w;
    }
    float4 un = u[(boff + n) * SEG4 + r4];
    float c2 = 2.0f / lamp[0];
    float dn = g_deg[n];
    float4 r;
    r.x = c2 * (dn * un.x - acc.x) - un.x;
    r.y = c2 * (dn * un.y - acc.y) - un.y;
    r.z = c2 * (dn * un.z - acc.z) - un.z;
    r.w = c2 * (dn * un.w - acc.w) - un.w;
    ((float4*)g_Tx1)[(boff + n) * SEG4 + r4] = r;
}

// Tx2 = 2*Lhat(Tx1) - x
__global__ void k_lhat2(const float* __restrict__ x, const float* __restrict__ lamp) {
    int n = blockIdx.x, j = threadIdx.x;
    int b = j / SEG4, r4 = j - b * SEG4;
    int boff = b * Nn;
    const float4* u = (const float4*)g_Tx1;
    float4 acc = make_float4(0.f, 0.f, 0.f, 0.f);
    int e = g_off[n], e1 = g_off[n + 1];
    for (; e + 4 <= e1; e += 4) {
        int s0 = g_srcs[e], s1 = g_srcs[e + 1], s2 = g_srcs[e + 2], s3 = g_srcs[e + 3];
        float4 v0 = u[(boff + s0) * SEG4 + r4], v1 = u[(boff + s1) * SEG4 + r4];
        float4 v2 = u[(boff + s2) * SEG4 + r4], v3 = u[(boff + s3) * SEG4 + r4];
        acc.x += (v0.x + v1.x) + (v2.x + v3.x);
        acc.y += (v0.y + v1.y) + (v2.y + v3.y);
        acc.z += (v0.z + v1.z) + (v2.z + v3.z);
        acc.w += (v0.w + v1.w) + (v2.w + v3.w);
    }
    for (; e < e1; e++) {
        float4 v = u[(boff + g_srcs[e]) * SEG4 + r4];
        acc.x += v.x; acc.y += v.y; acc.z += v.z; acc.w += v.w;
    }
    float4 un = u[(boff + n) * SEG4 + r4];
    float4 t0 = ((const float4*)x)[(boff + n) * SEG4 + r4];
    float c2 = 2.0f / lamp[0];
    float dn = g_deg[n];
    float4 r;
    r.x = 2.0f * (c2 * (dn * un.x - acc.x) - un.x) - t0.x;
    r.y = 2.0f * (c2 * (dn * un.y - acc.y) - un.y) - t0.y;
    r.z = 2.0f * (c2 * (dn * un.z - acc.z) - un.z) - t0.z;
    r.w = 2.0f * (c2 * (dn * un.w - acc.w) - un.w) - t0.w;
    ((float4*)g_Tx2)[(boff + n) * SEG4 + r4] = r;
}

// ---------------- fused: tensor Stage A + FFMA2 conv/res + LN ----------------
// Stage A: spatial(12t x 64c) = A(12x48) @ chebW(48x64) via mma.m16n8k16.bf16
// with 2-plane split (h + m); rows 12..15 of the A tile are zero padding.
// Stage B (temporal conv + residual) unchanged f32x2 path.
//
// Block smem (float units):
//   [0,1536)       Wch_h  bf16[64 c][48 j]   (transposed, k-contiguous)
//   [1536,3072)    Wch_m  bf16[64][48]
//   [3072,15360)   wtu    f32x2 time weights [d(3)][cip(32)][c(64)]
//   [15360,16384)  wru    f32x2 res weights  [fp(8)][c(64)]
//   [16384,16640)  cb/trb/gma/bta
// Per group (stride 2648, base 16640):
//   +0    Ah bf16[16][48]  (384 float-slots)
//   +384  Am bf16[16][48]
//   +768  myspad (896)   +1664 myxr (192)   +1856 myhs (768)
//   +2624 mymu(12) +2636 myrs(12)
#define GB_BASE 16640
#define GB_STRIDE 2648
#define SMEM_FLOATS (GB_BASE + 4 * GB_STRIDE)   // 27232 floats = 108928 B

__global__ void __launch_bounds__(256, 2)
k_fused(const float* __restrict__ x,
        const float* __restrict__ chebW, const float* __restrict__ chebB,
        const float* __restrict__ timeW, const float* __restrict__ timeB,
        const float* __restrict__ resW,  const float* __restrict__ resB,
        const float* __restrict__ gamma, const float* __restrict__ beta,
        float* __restrict__ out)
{
    extern __shared__ float sm[];
    bf16* Wh = (bf16*)sm;                 // [c*48 + j]
    bf16* Wm = (bf16*)(sm + 1536);
    float* cb  = sm + 16384;
    float* trb = sm + 16448;
    float* gma = sm + 16512;
    float* bta = sm + 16576;
    const u64* wtu = (const u64*)(sm + 3072);   // [d*2048 + cip*64 + c]
    const u64* wru = (const u64*)(sm + 15360);  // [fp*64 + c]

    int tid = threadIdx.x;

    // --- one-time weight staging ---
    for (int i = tid; i < 3072; i += 256) {          // cheb split planes
        int c = i / 48, j = i - c * 48;
        float w = chebW[j * 64 + c];
        bf16 h = __float2bfloat16(w);
        bf16 m = __float2bfloat16(w - __bfloat162float(h));
        Wh[i] = h; Wm[i] = m;
    }
    for (int i = tid; i < 6144; i += 256) {          // time: d(3), cip(32), c(64)
        int d = i >> 11; int r = i & 2047;
        int cip = r >> 6; int c = r & 63;
        sm[3072 + 2 * i]     = timeW[c * 192 + (2 * cip) * 3 + d];
        sm[3072 + 2 * i + 1] = timeW[c * 192 + (2 * cip + 1) * 3 + d];
    }
    for (int i = tid; i < 512; i += 256) {           // res: fp(8), c(64)
        int fp = i >> 6, c = i & 63;
        sm[15360 + 2 * i]     = resW[c * 16 + 2 * fp];
        sm[15360 + 2 * i + 1] = resW[c * 16 + 2 * fp + 1];
    }
    if (tid < 64) {
        cb[tid]  = chebB[tid];
        trb[tid] = timeB[tid] + resB[tid];
        gma[tid] = gamma[tid];
        bta[tid] = beta[tid];
    }

    const int g = tid >> 6;        // group = batch b
    const int c = tid & 63;
    const int lane = tid & 31;
    const int w01 = (tid >> 5) & 1;

    float* gbase  = sm + GB_BASE + g * GB_STRIDE;
    bf16*  Ah     = (bf16*)gbase;           // [t(16)][j(48)]
    bf16*  Am     = (bf16*)(gbase + 384);
    float* myspad = gbase + 768;            // u64[cip(32)][tpos(14)]
    float* myxr   = gbase + 1664;           // u64[fp(8)][t(12)]
    float* myhs   = gbase + 1856;           // [t(12)][c(64)]
    float* mymu   = gbase + 2624;
    float* myrs   = gbase + 2636;

    // one-time per-group init: spad boundaries + A-plane zero rows 12..15
    {
        float* sp = myspad + (c >> 1) * 28 + (c & 1);
        sp[0] = 0.f; sp[26] = 0.f;
        for (int i = c; i < 192; i += 64) {
            Ah[12 * 48 + i] = __float2bfloat16(0.f);
            Am[12 * 48 + i] = __float2bfloat16(0.f);
        }
    }
    __syncthreads();   // weights + inits visible

    for (int q = blockIdx.x; q < Nn; q += gridDim.x) {
        const int n = q;
        const size_t rowbase = (size_t)(g * Nn + n) * SEG;

        // ---- Stage 0: load 3 fields, build bf16 split planes (+ fp32 xr) ----
        {
            const float* px  = x      + rowbase;
            const float* p1  = g_Tx1  + rowbase;
            const float* p2  = g_Tx2  + rowbase;
#pragma unroll
            for (int rep = 0; rep < 3; rep++) {
                int rr = rep * 64 + c;          // rr = f*12 + t
                int f = rr / 12, t = rr - f * 12;
                float vx = px[rr];
                myxr[(f >> 1) * 24 + t * 2 + (f & 1)] = vx;
                {   bf16 h = __float2bfloat16(vx);
                    Ah[t * 48 + f] = h;
                    Am[t * 48 + f] = __float2bfloat16(vx - __bfloat162float(h)); }
                float v1 = p1[rr];
                {   bf16 h = __float2bfloat16(v1);
                    Ah[t * 48 + 16 + f] = h;
                    Am[t * 48 + 16 + f] = __float2bfloat16(v1 - __bfloat162float(h)); }
                float v2 = p2[rr];
                {   bf16 h = __float2bfloat16(v2);
                    Ah[t * 48 + 32 + f] = h;
                    Am[t * 48 + 32 + f] = __float2bfloat16(v2 - __bfloat162float(h)); }
            }
        }
        GROUP_BAR(g);

        // ---- Stage A: tensor-core cheb projection -> relu -> spad ----
        {
            float C[4][4];
#pragma unroll
            for (int nt = 0; nt < 4; nt++)
#pragma unroll
                for (int r = 0; r < 4; r++) C[nt][r] = 0.f;

            const int arow = lane >> 2;          // 0..7
            const int alo  = (lane & 3) * 2;
#pragma unroll
            for (int kt = 0; kt < 3; kt++) {
                uint32_t ah[4], am[4];
                int acol = kt * 16 + alo;
                ah[0] = *(const uint32_t*)(Ah + arow * 48 + acol);
                ah[1] = *(const uint32_t*)(Ah + (arow + 8) * 48 + acol);
                ah[2] = *(const uint32_t*)(Ah + arow * 48 + acol + 8);
                ah[3] = *(const uint32_t*)(Ah + (arow + 8) * 48 + acol + 8);
                am[0] = *(const uint32_t*)(Am + arow * 48 + acol);
                am[1] = *(const uint32_t*)(Am + (arow + 8) * 48 + acol);
                am[2] = *(const uint32_t*)(Am + arow * 48 + acol + 8);
                am[3] = *(const uint32_t*)(Am + (arow + 8) * 48 + acol + 8);
#pragma unroll
                for (int nt = 0; nt < 4; nt++) {
                    int bcol = w01 * 32 + nt * 8 + (lane >> 2);
                    int brow = kt * 16 + alo;
                    uint32_t bh0 = *(const uint32_t*)(Wh + bcol * 48 + brow);
                    uint32_t bh1 = *(const uint32_t*)(Wh + bcol * 48 + brow + 8);
                    uint32_t bm0 = *(const uint32_t*)(Wm + bcol * 48 + brow);
                    uint32_t bm1 = *(const uint32_t*)(Wm + bcol * 48 + brow + 8);
                    mma_bf16(C[nt], ah, bh0, bh1);
                    mma_bf16(C[nt], ah, bm0, bm1);
                    mma_bf16(C[nt], am, bh0, bh1);
                }
            }
            // epilogue: bias + relu -> spad (pair-interleaved layout)
            int t0 = lane >> 2;          // rows 0..7 (always valid)
            int t1 = t0 + 8;             // rows 8..15 (valid if < 12)
#pragma unroll
            for (int nt = 0; nt < 4; nt++) {
                int ccol = w01 * 32 + nt * 8 + (lane & 3) * 2;   // even
                float* p = myspad + (ccol >> 1) * 28;
                float b0 = cb[ccol], b1 = cb[ccol + 1];
                p[(t0 + 1) * 2 + 0] = fmaxf(C[nt][0] + b0, 0.f);
                p[(t0 + 1) * 2 + 1] = fmaxf(C[nt][1] + b1, 0.f);
                if (t1 < 12) {
                    p[(t1 + 1) * 2 + 0] = fmaxf(C[nt][2] + b0, 0.f);
                    p[(t1 + 1) * 2 + 1] = fmaxf(C[nt][3] + b1, 0.f);
                }
            }
        }
        GROUP_BAR(g);

        // ---- Stage B: temporal conv + residual in two 6-t half-passes (f32x2) ----
        float h[12];
        {
            float bb = trb[c];
#pragma unroll
            for (int half = 0; half < 2; half++) {
                u64 acc[6];
#pragma unroll
                for (int tt = 0; tt < 6; tt++) acc[tt] = 0ull;
#pragma unroll 1
                for (int cip = 0; cip < 32; cip++) {
                    const ulonglong2* row =
                        (const ulonglong2*)(myspad + cip * 28 + 12 * half);
                    ulonglong2 q0 = row[0], q1 = row[1], q2 = row[2], q3 = row[3];
                    u64 w0 = wtu[cip * 64 + c];
                    u64 w1 = wtu[2048 + cip * 64 + c];
                    u64 w2 = wtu[4096 + cip * 64 + c];
                    acc[0] = ffma2(q0.x, w0, acc[0]);
                    acc[0] = ffma2(q0.y, w1, acc[0]);
                    acc[0] = ffma2(q1.x, w2, acc[0]);
                    acc[1] = ffma2(q0.y, w0, acc[1]);
                    acc[1] = ffma2(q1.x, w1, acc[1]);
                    acc[1] = ffma2(q1.y, w2, acc[1]);
                    acc[2] = ffma2(q1.x, w0, acc[2]);
                    acc[2] = ffma2(q1.y, w1, acc[2]);
                    acc[2] = ffma2(q2.x, w2, acc[2]);
                    acc[3] = ffma2(q1.y, w0, acc[3]);
                    acc[3] = ffma2(q2.x, w1, acc[3]);
                    acc[3] = ffma2(q2.y, w2, acc[3]);
                    acc[4] = ffma2(q2.x, w0, acc[4]);
                    acc[4] = ffma2(q2.y, w1, acc[4]);
                    acc[4] = ffma2(q3.x, w2, acc[4]);
                    acc[5] = ffma2(q2.y, w0, acc[5]);
                    acc[5] = ffma2(q3.x, w1, acc[5]);
                    acc[5] = ffma2(q3.y, w2, acc[5]);
                }
#pragma unroll 2
                for (int fp = 0; fp < 8; fp++) {
                    const ulonglong2* row =
                        (const ulonglong2*)(myxr + fp * 24 + 12 * half);
                    ulonglong2 p0 = row[0], p1 = row[1], p2 = row[2];
                    u64 w = wru[fp * 64 + c];
                    acc[0] = ffma2(p0.x, w, acc[0]);
                    acc[1] = ffma2(p0.y, w, acc[1]);
                    acc[2] = ffma2(p1.x, w, acc[2]);
                    acc[3] = ffma2(p1.y, w, acc[3]);
                    acc[4] = ffma2(p2.x, w, acc[4]);
                    acc[5] = ffma2(p2.y, w, acc[5]);
                }
#pragma unroll
                for (int tt = 0; tt < 6; tt++) {
                    int t = half * 6 + tt;
                    h[t] = fmaxf(hsum2(acc[tt]) + bb, 0.f);
                    myhs[t * 64 + c] = h[t];
                }
            }
        }
        GROUP_BAR(g);

        // ---- LN stats ----
        {
#pragma unroll
            for (int r = 0; r < 6; r++) {
                int t = w01 * 6 + r;
                float v1 = myhs[t * 64 + lane];
                float v2 = myhs[t * 64 + 32 + lane];
                float s = v1 + v2;
                float sq = v1 * v1 + v2 * v2;
#pragma unroll
                for (int o = 16; o > 0; o >>= 1) {
                    s  += __shfl_xor_sync(0xffffffffu, s, o);
                    sq += __shfl_xor_sync(0xffffffffu, sq, o);
                }
                if (lane == 0) {
                    float mu = s * (1.0f / 64.0f);
                    float var = sq * (1.0f / 64.0f) - mu * mu;
                    mymu[t] = mu;
                    myrs[t] = rsqrtf(var + 1e-5f);
                }
            }
        }
        GROUP_BAR(g);

        // ---- normalize + write out (B,N,C,T) ----
        {
            float ga = gma[c], be = bta[c];
            float o[12];
#pragma unroll
            for (int t = 0; t < 12; t++)
                o[t] = (h[t] - mymu[t]) * myrs[t] * ga + be;
            float* op = out + (((size_t)g * Nn + n) * 64 + c) * 12;
            float4* op4 = (float4*)op;
            op4[0] = make_float4(o[0], o[1], o[2],  o[3]);
            op4[1] = make_float4(o[4], o[5], o[6],  o[7]);
            op4[2] = make_float4(o[8], o[9], o[10], o[11]);
        }
        GROUP_BAR(g);  // protect planes/spad from next tile's stage-0
    }
}

// ---------------- launcher ----------------
extern "C" void kernel_launch(void* const* d_in, const int* in_sizes, int n_in,
                              void* d_out, int out_size)
{
    const float* x     = (const float*)d_in[0];
    const int*   ei    = (const int*)d_in[1];
    const float* lam   = (const float*)d_in[2];
    const float* chebW = (const float*)d_in[3];
    const float* chebB = (const float*)d_in[4];
    const float* timeW = (const float*)d_in[5];
    const float* timeB = (const float*)d_in[6];
    const float* resW  = (const float*)d_in[7];
    const float* resB  = (const float*)d_in[8];
    const float* gma   = (const float*)d_in[9];
    const float* bta   = (const float*)d_in[10];
    float* out = (float*)d_out;

    k_zero<<<(Nn + 255) / 256, 256>>>();
    k_count<<<(Ee + 255) / 256, 256>>>(ei);
    k_scan<<<1, 1024>>>();
    k_fill<<<(Ee + 255) / 256, 256>>>(ei);
    k_lhat1<<<Nn, 192>>>(x, lam);
    k_lhat2<<<Nn, 192>>>(x, lam);

    cudaFuncSetAttribute(k_fused, cudaFuncAttributeMaxDynamicSharedMemorySize,
                         SMEM_FLOATS * 4);
    k_fused<<<296, 256, SMEM_FLOATS * 4>>>(x, chebW, chebB, timeW, timeB,
                                           resW, resB, gma, bta, out);
}

// round 7
// speedup vs baseline: 1.8203x; 1.6593x over previous
#include <cuda_runtime.h>
#include <cuda_bf16.h>
#include <cstdint>

// Problem constants
#define Nn   10000
#define Bb   4
#define Ff   16
#define Tt   12
#define Ee   160000
#define Cc   64
#define ROW  768          // Bb*Tt*Ff floats per node (4 segments of 192)
#define SEG  192          // floats per (n,b) row
#define SEG4 48           // float4 per (n,b) row

typedef unsigned long long u64;
typedef __nv_bfloat16 bf16;

#define GROUP_BAR(gid) asm volatile("bar.sync %0, 64;" :: "r"((gid) + 1) : "memory")

__device__ __forceinline__ void mma_bf16(float c[4], const uint32_t a[4],
                                         uint32_t b0, uint32_t b1) {
    asm volatile(
        "mma.sync.aligned.m16n8k16.row.col.f32.bf16.bf16.f32 "
        "{%0,%1,%2,%3}, {%4,%5,%6,%7}, {%8,%9}, {%0,%1,%2,%3};"
        : "+f"(c[0]), "+f"(c[1]), "+f"(c[2]), "+f"(c[3])
        : "r"(a[0]), "r"(a[1]), "r"(a[2]), "r"(a[3]), "r"(b0), "r"(b1));
}

__device__ __forceinline__ uint32_t pk2(float a, float b) {
    __nv_bfloat162 t = __floats2bfloat162_rn(a, b);
    return *reinterpret_cast<uint32_t*>(&t);
}

// ---------------- scratch (device globals; no allocation) ----------------
__device__ float g_Tx1[Nn * ROW];
__device__ float g_Tx2[Nn * ROW];
__device__ float g_deg[Nn];
__device__ int   g_degin[Nn];
__device__ int   g_off[Nn + 1];
__device__ int   g_cur[Nn];
__device__ int   g_srcs[Ee];

// ---------------- graph preprocessing ----------------
__global__ void k_zero() {
    int i = blockIdx.x * blockDim.x + threadIdx.x;
    if (i < Nn) { g_deg[i] = 0.0f; g_degin[i] = 0; }
}

__global__ void k_count(const int* __restrict__ ei) {
    int e = blockIdx.x * blockDim.x + threadIdx.x;
    if (e < Ee) {
        atomicAdd(&g_deg[ei[e]], 1.0f);
        atomicAdd(&g_degin[ei[Ee + e]], 1);
    }
}

__global__ void k_scan() {
    __shared__ int part[1024];
    int t = threadIdx.x;
    const int CH = 10;
    int base = t * CH;
    int local[CH];
    int s = 0;
#pragma unroll
    for (int i = 0; i < CH; i++) {
        int idx = base + i;
        int v = (idx < Nn) ? g_degin[idx] : 0;
        local[i] = v; s += v;
    }
    part[t] = s;
    __syncthreads();
    for (int off = 1; off < 1024; off <<= 1) {
        int v = (t >= off) ? part[t - off] : 0;
        __syncthreads();
        part[t] += v;
        __syncthreads();
    }
    int pre = (t == 0) ? 0 : part[t - 1];
#pragma unroll
    for (int i = 0; i < CH; i++) {
        int idx = base + i;
        if (idx < Nn) { g_off[idx] = pre; g_cur[idx] = pre; pre += local[i]; }
    }
    if (t == 1023) g_off[Nn] = part[1023];
}

__global__ void k_fill(const int* __restrict__ ei) {
    int e = blockIdx.x * blockDim.x + threadIdx.x;
    if (e < Ee) {
        int c = ei[Ee + e];
        int p = atomicAdd(&g_cur[c], 1);
        g_srcs[p] = ei[e];
    }
}

// ---------------- Lhat via CSR gather, in x's native (b,n,f,t) layout ----------------
__global__ void k_lhat1(const float* __restrict__ x, const float* __restrict__ lamp) {
    int n = blockIdx.x, j = threadIdx.x;
    int b = j / SEG4, r4 = j - b * SEG4;
    int boff = b * Nn;
    const float4* u = (const float4*)x;
    float4 acc = make_float4(0.f, 0.f, 0.f, 0.f);
    int e = g_off[n], e1 = g_off[n + 1];
    for (; e + 4 <= e1; e += 4) {
        int s0 = g_srcs[e], s1 = g_srcs[e + 1], s2 = g_srcs[e + 2], s3 = g_srcs[e + 3];
        float4 v0 = u[(boff + s0) * SEG4 + r4], v1 = u[(boff + s1) * SEG4 + r4];
        float4 v2 = u[(boff + s2) * SEG4 + r4], v3 = u[(boff + s3) * SEG4 + r4];
        acc.x += (v0.x + v1.x) + (v2.x + v3.x);
        acc.y += (v0.y + v1.y) + (v2.y + v3.y);
        acc.z += (v0.z + v1.z) + (v2.z + v3.z);
        acc.w += (v0.w + v1.w) + (v2.w + v3.w);
    }
    for (; e < e1; e++) {
        float4 v = u[(boff + g_srcs[e]) * SEG4 + r4];
        acc.x += v.x; acc.y += v.y; acc.z += v.z; acc.w += v.w;
    }
    float4 un = u[(boff + n) * SEG4 + r4];
    float c2 = 2.0f / lamp[0];
    float dn = g_deg[n];
    float4 r;
    r.x = c2 * (dn * un.x - acc.x) - un.x;
    r.y = c2 * (dn * un.y - acc.y) - un.y;
    r.z = c2 * (dn * un.z - acc.z) - un.z;
    r.w = c2 * (dn * un.w - acc.w) - un.w;
    ((float4*)g_Tx1)[(boff + n) * SEG4 + r4] = r;
}

__global__ void k_lhat2(const float* __restrict__ x, const float* __restrict__ lamp) {
    int n = blockIdx.x, j = threadIdx.x;
    int b = j / SEG4, r4 = j - b * SEG4;
    int boff = b * Nn;
    const float4* u = (const float4*)g_Tx1;
    float4 acc = make_float4(0.f, 0.f, 0.f, 0.f);
    int e = g_off[n], e1 = g_off[n + 1];
    for (; e + 4 <= e1; e += 4) {
        int s0 = g_srcs[e], s1 = g_srcs[e + 1], s2 = g_srcs[e + 2], s3 = g_srcs[e + 3];
        float4 v0 = u[(boff + s0) * SEG4 + r4], v1 = u[(boff + s1) * SEG4 + r4];
        float4 v2 = u[(boff + s2) * SEG4 + r4], v3 = u[(boff + s3) * SEG4 + r4];
        acc.x += (v0.x + v1.x) + (v2.x + v3.x);
        acc.y += (v0.y + v1.y) + (v2.y + v3.y);
        acc.z += (v0.z + v1.z) + (v2.z + v3.z);
        acc.w += (v0.w + v1.w) + (v2.w + v3.w);
    }
    for (; e < e1; e++) {
        float4 v = u[(boff + g_srcs[e]) * SEG4 + r4];
        acc.x += v.x; acc.y += v.y; acc.z += v.z; acc.w += v.w;
    }
    float4 un = u[(boff + n) * SEG4 + r4];
    float4 t0 = ((const float4*)x)[(boff + n) * SEG4 + r4];
    float c2 = 2.0f / lamp[0];
    float dn = g_deg[n];
    float4 r;
    r.x = 2.0f * (c2 * (dn * un.x - acc.x) - un.x) - t0.x;
    r.y = 2.0f * (c2 * (dn * un.y - acc.y) - un.y) - t0.y;
    r.z = 2.0f * (c2 * (dn * un.z - acc.z) - un.z) - t0.z;
    r.w = 2.0f * (c2 * (dn * un.w - acc.w) - un.w) - t0.w;
    ((float4*)g_Tx2)[(boff + n) * SEG4 + r4] = r;
}

// ---------------- fully-tensor fused kernel ----------------
// Stage A: spatial = A(12x48) @ chebW(48x64), bf16 2-plane split MMA.
// Stage B: temporal conv as 3 row-shifted GEMMs over S(18x64) + residual GEMM
//          reusing the x plane (cheb k=0 cols of Ah). All B operands staged
//          fragment-ordered (1 LDS.128 per fragment quad).
//
// smem (floats):
//   WF   [0,16384)      fragment-ordered weights: 128 chunks x 32 lanes x 16B
//                       chunks 0..23 cheb(kt*8+nt), 24..119 conv(24+d*32+kt*8+nt),
//                       120..127 residual(nt)
//   cb/trb/gma/bta [16384,16640)
// per group (base 16640, stride 2984):
//   Ah  +0    (448)  bf16[16 t][56]  cols j=k*16+f (k=0 plane = x, reused by residual)
//   Am  +448  (448)
//   Sh  +896  (648)  bf16[18 tpos][72]  (rows 0,13 zero = conv padding)
//   Sm  +1544 (648)
//   myhs +2192 (768) f32[12 t][64 c]
//   mymu +2960 (12)  myrs +2972 (12)
#define GB_BASE 16640
#define GB_STRIDE 2984
#define SMEM_FLOATS (GB_BASE + 4 * GB_STRIDE)   // 28576 floats = 114304 B

__global__ void __launch_bounds__(256, 2)
k_fused(const float* __restrict__ x,
        const float* __restrict__ chebW, const float* __restrict__ chebB,
        const float* __restrict__ timeW, const float* __restrict__ timeB,
        const float* __restrict__ resW,  const float* __restrict__ resB,
        const float* __restrict__ gamma, const float* __restrict__ beta,
        float* __restrict__ out)
{
    extern __shared__ float sm[];
    uint32_t* WFu = (uint32_t*)sm;
    float* cb  = sm + 16384;
    float* trb = sm + 16448;
    float* gma = sm + 16512;
    float* bta = sm + 16576;

    int tid = threadIdx.x;

    // --- one-time fragment-ordered weight staging (h/m split planes) ---
    for (int e = tid; e < 128 * 32; e += 256) {
        int chunk = e >> 5, ln = e & 31;
        int half = ln >> 2;            // n within 8-col tile
        int kp = (ln & 3) * 2;         // k row base
        float w0, w1, w2, w3;
        if (chunk < 24) {              // cheb
            int kt = chunk >> 3, nt = chunk & 7;
            int bcol = nt * 8 + half;
            int r = kt * 16 + kp;
            w0 = chebW[r * 64 + bcol];       w1 = chebW[(r + 1) * 64 + bcol];
            w2 = chebW[(r + 8) * 64 + bcol]; w3 = chebW[(r + 9) * 64 + bcol];
        } else if (chunk < 120) {      // conv taps
            int q = chunk - 24;
            int d = q >> 5, kt = (q >> 3) & 3, nt = q & 7;
            int bcol = nt * 8 + half;
            int ci = kt * 16 + kp;
            w0 = timeW[bcol * 192 + ci * 3 + d];
            w1 = timeW[bcol * 192 + (ci + 1) * 3 + d];
            w2 = timeW[bcol * 192 + (ci + 8) * 3 + d];
            w3 = timeW[bcol * 192 + (ci + 9) * 3 + d];
        } else {                       // residual
            int nt = chunk - 120;
            int bcol = nt * 8 + half;
            w0 = resW[bcol * 16 + kp];     w1 = resW[bcol * 16 + kp + 1];
            w2 = resW[bcol * 16 + kp + 8]; w3 = resW[bcol * 16 + kp + 9];
        }
        float h0 = __bfloat162float(__float2bfloat16(w0));
        float h1 = __bfloat162float(__float2bfloat16(w1));
        float h2 = __bfloat162float(__float2bfloat16(w2));
        float h3 = __bfloat162float(__float2bfloat16(w3));
        uint32_t* p = WFu + chunk * 128 + ln * 4;
        p[0] = pk2(w0, w1);
        p[1] = pk2(w2, w3);
        p[2] = pk2(w0 - h0, w1 - h1);
        p[3] = pk2(w2 - h2, w3 - h3);
    }
    if (tid < 64) {
        cb[tid]  = chebB[tid];
        trb[tid] = timeB[tid] + resB[tid];
        gma[tid] = gamma[tid];
        bta[tid] = beta[tid];
    }

    const int g = tid >> 6;        // group = batch b
    const int c = tid & 63;
    const int lane = tid & 31;
    const int w01 = (tid >> 5) & 1;
    const int gr = lane >> 2;
    const int qk = (lane & 3) * 2;

    float* gbase = sm + GB_BASE + g * GB_STRIDE;
    bf16*  Ah    = (bf16*)gbase;            // [16][56]
    bf16*  Am    = (bf16*)(gbase + 448);
    bf16*  Sh    = (bf16*)(gbase + 896);    // [18][72]
    bf16*  Sm    = (bf16*)(gbase + 1544);
    float* myhs  = gbase + 2192;            // [12][64]
    float* mymu  = gbase + 2960;
    float* myrs  = gbase + 2972;

    // one-time per-group init: S zero-padding rows 0 and 13 (cols 0..63)
    {
        bf16 z = __float2bfloat16(0.f);
        Sh[0 * 72 + c]  = z; Sh[13 * 72 + c] = z;
        Sm[0 * 72 + c]  = z; Sm[13 * 72 + c] = z;
    }
    __syncthreads();   // weights + inits visible

    for (int q = blockIdx.x; q < Nn; q += gridDim.x) {
        const int n = q;
        const size_t rowbase = (size_t)(g * Nn + n) * SEG;

        // ---- Stage 0: load x/Tx1/Tx2, build bf16 split A planes ----
        {
            const float* px = x     + rowbase;
            const float* p1 = g_Tx1 + rowbase;
            const float* p2 = g_Tx2 + rowbase;
#pragma unroll
            for (int rep = 0; rep < 3; rep++) {
                int rr = rep * 64 + c;          // rr = f*12 + t
                int f = rr / 12, t = rr - f * 12;
                float vx = px[rr];
                {   bf16 h = __float2bfloat16(vx);
                    Ah[t * 56 + f] = h;
                    Am[t * 56 + f] = __float2bfloat16(vx - __bfloat162float(h)); }
                float v1 = p1[rr];
                {   bf16 h = __float2bfloat16(v1);
                    Ah[t * 56 + 16 + f] = h;
                    Am[t * 56 + 16 + f] = __float2bfloat16(v1 - __bfloat162float(h)); }
                float v2 = p2[rr];
                {   bf16 h = __float2bfloat16(v2);
                    Ah[t * 56 + 32 + f] = h;
                    Am[t * 56 + 32 + f] = __float2bfloat16(v2 - __bfloat162float(h)); }
            }
        }
        GROUP_BAR(g);

        // ---- Stage A: tensor cheb projection -> relu -> S split planes ----
        {
            float CA[4][4];
#pragma unroll
            for (int nt = 0; nt < 4; nt++)
#pragma unroll
                for (int r = 0; r < 4; r++) CA[nt][r] = 0.f;

#pragma unroll
            for (int kt = 0; kt < 3; kt++) {
                int acol = kt * 16 + qk;
                uint32_t ah[4], am[4];
                ah[0] = *(const uint32_t*)(Ah + gr * 56 + acol);
                ah[1] = *(const uint32_t*)(Ah + (gr + 8) * 56 + acol);
                ah[2] = *(const uint32_t*)(Ah + gr * 56 + acol + 8);
                ah[3] = *(const uint32_t*)(Ah + (gr + 8) * 56 + acol + 8);
                am[0] = *(const uint32_t*)(Am + gr * 56 + acol);
                am[1] = *(const uint32_t*)(Am + (gr + 8) * 56 + acol);
                am[2] = *(const uint32_t*)(Am + gr * 56 + acol + 8);
                am[3] = *(const uint32_t*)(Am + (gr + 8) * 56 + acol + 8);
                int cbase = kt * 8 + w01 * 4;
#pragma unroll
                for (int ntl = 0; ntl < 4; ntl++) {
                    uint4 wb = *(const uint4*)(WFu + (cbase + ntl) * 128 + lane * 4);
                    mma_bf16(CA[ntl], ah, wb.x, wb.y);
                    mma_bf16(CA[ntl], ah, wb.z, wb.w);
                    mma_bf16(CA[ntl], am, wb.x, wb.y);
                }
            }
            // epilogue: bias+relu -> bf16 split -> S rows tpos=t+1
#pragma unroll
            for (int ntl = 0; ntl < 4; ntl++) {
                int ccol = w01 * 32 + ntl * 8 + qk;
                float b0 = cb[ccol], b1 = cb[ccol + 1];
                float v0 = fmaxf(CA[ntl][0] + b0, 0.f);
                float v1 = fmaxf(CA[ntl][1] + b1, 0.f);
                float h0 = __bfloat162float(__float2bfloat16(v0));
                float h1 = __bfloat162float(__float2bfloat16(v1));
                *(uint32_t*)(Sh + (gr + 1) * 72 + ccol) = pk2(v0, v1);
                *(uint32_t*)(Sm + (gr + 1) * 72 + ccol) = pk2(v0 - h0, v1 - h1);
                if (gr < 4) {
                    float v2 = fmaxf(CA[ntl][2] + b0, 0.f);
                    float v3 = fmaxf(CA[ntl][3] + b1, 0.f);
                    float h2 = __bfloat162float(__float2bfloat16(v2));
                    float h3 = __bfloat162float(__float2bfloat16(v3));
                    *(uint32_t*)(Sh + (gr + 9) * 72 + ccol) = pk2(v2, v3);
                    *(uint32_t*)(Sm + (gr + 9) * 72 + ccol) = pk2(v2 - h2, v3 - h3);
                }
            }
        }
        GROUP_BAR(g);

        // ---- Stage B: conv (3 shifted GEMMs) + residual GEMM ----
        {
            float CB[4][4];
#pragma unroll
            for (int nt = 0; nt < 4; nt++)
#pragma unroll
                for (int r = 0; r < 4; r++) CB[nt][r] = 0.f;

#pragma unroll
            for (int d = 0; d < 3; d++) {
#pragma unroll
                for (int kt = 0; kt < 4; kt++) {
                    int acol = kt * 16 + qk;
                    int ar = d + gr;
                    uint32_t ah[4], am[4];
                    ah[0] = *(const uint32_t*)(Sh + ar * 72 + acol);
                    ah[1] = *(const uint32_t*)(Sh + (ar + 8) * 72 + acol);
                    ah[2] = *(const uint32_t*)(Sh + ar * 72 + acol + 8);
                    ah[3] = *(const uint32_t*)(Sh + (ar + 8) * 72 + acol + 8);
                    am[0] = *(const uint32_t*)(Sm + ar * 72 + acol);
                    am[1] = *(const uint32_t*)(Sm + (ar + 8) * 72 + acol);
                    am[2] = *(const uint32_t*)(Sm + ar * 72 + acol + 8);
                    am[3] = *(const uint32_t*)(Sm + (ar + 8) * 72 + acol + 8);
                    int cbase = 24 + d * 32 + kt * 8 + w01 * 4;
#pragma unroll
                    for (int ntl = 0; ntl < 4; ntl++) {
                        uint4 wb = *(const uint4*)(WFu + (cbase + ntl) * 128 + lane * 4);
                        mma_bf16(CB[ntl], ah, wb.x, wb.y);
                        mma_bf16(CB[ntl], ah, wb.z, wb.w);
                        mma_bf16(CB[ntl], am, wb.x, wb.y);
                    }
                }
            }
            // residual GEMM: A = x plane (Ah cols 0..15)
            {
                uint32_t ah[4], am[4];
                ah[0] = *(const uint32_t*)(Ah + gr * 56 + qk);
                ah[1] = *(const uint32_t*)(Ah + (gr + 8) * 56 + qk);
                ah[2] = *(const uint32_t*)(Ah + gr * 56 + qk + 8);
                ah[3] = *(const uint32_t*)(Ah + (gr + 8) * 56 + qk + 8);
                am[0] = *(const uint32_t*)(Am + gr * 56 + qk);
                am[1] = *(const uint32_t*)(Am + (gr + 8) * 56 + qk);
                am[2] = *(const uint32_t*)(Am + gr * 56 + qk + 8);
                am[3] = *(const uint32_t*)(Am + (gr + 8) * 56 + qk + 8);
                int cbase = 120 + w01 * 4;
#pragma unroll
                for (int ntl = 0; ntl < 4; ntl++) {
                    uint4 wb = *(const uint4*)(WFu + (cbase + ntl) * 128 + lane * 4);
                    mma_bf16(CB[ntl], ah, wb.x, wb.y);
                    mma_bf16(CB[ntl], ah, wb.z, wb.w);
                    mma_bf16(CB[ntl], am, wb.x, wb.y);
                }
            }
            // epilogue: bias + relu -> myhs (f32)
#pragma unroll
            for (int ntl = 0; ntl < 4; ntl++) {
                int ccol = w01 * 32 + ntl * 8 + qk;
                float b0 = trb[ccol], b1 = trb[ccol + 1];
                float2 v01 = make_float2(fmaxf(CB[ntl][0] + b0, 0.f),
                                         fmaxf(CB[ntl][1] + b1, 0.f));
                *(float2*)(myhs + gr * 64 + ccol) = v01;
                if (gr < 4) {
                    float2 v23 = make_float2(fmaxf(CB[ntl][2] + b0, 0.f),
                                             fmaxf(CB[ntl][3] + b1, 0.f));
                    *(float2*)(myhs + (gr + 8) * 64 + ccol) = v23;
                }
            }
        }
        GROUP_BAR(g);

        // ---- LN stats: each of the group's 2 warps reduces 6 t-rows ----
        {
#pragma unroll
            for (int r = 0; r < 6; r++) {
                int t = w01 * 6 + r;
                float v1 = myhs[t * 64 + lane];
                float v2 = myhs[t * 64 + 32 + lane];
                float s = v1 + v2;
                float sq = v1 * v1 + v2 * v2;
#pragma unroll
                for (int o = 16; o > 0; o >>= 1) {
                    s  += __shfl_xor_sync(0xffffffffu, s, o);
                    sq += __shfl_xor_sync(0xffffffffu, sq, o);
                }
                if (lane == 0) {
                    float mu = s * (1.0f / 64.0f);
                    float var = sq * (1.0f / 64.0f) - mu * mu;
                    mymu[t] = mu;
                    myrs[t] = rsqrtf(var + 1e-5f);
                }
            }
        }
        GROUP_BAR(g);

        // ---- normalize + write out (B,N,C,T), coalesced float4 ----
        {
            float ga = gma[c], be = bta[c];
            float o[12];
#pragma unroll
            for (int t = 0; t < 12; t++)
                o[t] = (myhs[t * 64 + c] - mymu[t]) * myrs[t] * ga + be;
            float* op = out + (((size_t)g * Nn + n) * 64 + c) * 12;
            float4* op4 = (float4*)op;
            op4[0] = make_float4(o[0], o[1], o[2],  o[3]);
            op4[1] = make_float4(o[4], o[5], o[6],  o[7]);
            op4[2] = make_float4(o[8], o[9], o[10], o[11]);
        }
        GROUP_BAR(g);  // myhs reads done before next tile's stage-B writes
    }
}

// ---------------- launcher ----------------
extern "C" void kernel_launch(void* const* d_in, const int* in_sizes, int n_in,
                              void* d_out, int out_size)
{
    const float* x     = (const float*)d_in[0];
    const int*   ei    = (const int*)d_in[1];
    const float* lam   = (const float*)d_in[2];
    const float* chebW = (const float*)d_in[3];
    const float* chebB = (const float*)d_in[4];
    const float* timeW = (const float*)d_in[5];
    const float* timeB = (const float*)d_in[6];
    const float* resW  = (const float*)d_in[7];
    const float* resB  = (const float*)d_in[8];
    const float* gma   = (const float*)d_in[9];
    const float* bta   = (const float*)d_in[10];
    float* out = (float*)d_out;

    k_zero<<<(Nn + 255) / 256, 256>>>();
    k_count<<<(Ee + 255) / 256, 256>>>(ei);
    k_scan<<<1, 1024>>>();
    k_fill<<<(Ee + 255) / 256, 256>>>(ei);
    k_lhat1<<<Nn, 192>>>(x, lam);
    k_lhat2<<<Nn, 192>>>(x, lam);

    cudaFuncSetAttribute(k_fused, cudaFuncAttributeMaxDynamicSharedMemorySize,
                         SMEM_FLOATS * 4);
    k_fused<<<296, 256, SMEM_FLOATS * 4>>>(x, chebW, chebB, timeW, timeB,
                                           resW, resB, gma, bta, out);
}

// round 8
// speedup vs baseline: 2.3169x; 1.2728x over previous
#include <cuda_runtime.h>
#include <cuda_bf16.h>
#include <cstdint>

// Problem constants
#define Nn   10000
#define Bb   4
#define Ff   16
#define Tt   12
#define Ee   160000
#define Cc   64
#define SEG  192          // floats per (n,b) row (f*12+t)
#define SEG4 48           // float4 per (n,b) row

typedef unsigned long long u64;
typedef __nv_bfloat16 bf16;

#define GROUP_BAR(gid) asm volatile("bar.sync %0, 64;" :: "r"((gid) + 1) : "memory")

__device__ __forceinline__ void mma_bf16(float c[4], const uint32_t a[4],
                                         uint32_t b0, uint32_t b1) {
    asm volatile(
        "mma.sync.aligned.m16n8k16.row.col.f32.bf16.bf16.f32 "
        "{%0,%1,%2,%3}, {%4,%5,%6,%7}, {%8,%9}, {%0,%1,%2,%3};"
        : "+f"(c[0]), "+f"(c[1]), "+f"(c[2]), "+f"(c[3])
        : "r"(a[0]), "r"(a[1]), "r"(a[2]), "r"(a[3]), "r"(b0), "r"(b1));
}

__device__ __forceinline__ uint32_t pk2(float a, float b) {
    __nv_bfloat162 t = __floats2bfloat162_rn(a, b);
    return *reinterpret_cast<uint32_t*>(&t);
}

// ---------------- scratch (device globals; no allocation) ----------------
__device__ float g_Tx1[Nn * Bb * SEG];
__device__ float g_Tx2[Nn * Bb * SEG];
__device__ float g_deg[Nn];
__device__ int   g_degin[Nn];
__device__ int   g_off[Nn + 1];
__device__ int   g_cur[Nn];
__device__ int   g_srcs[Ee];

// ---------------- graph preprocessing ----------------
__global__ void k_zero() {
    int i = blockIdx.x * blockDim.x + threadIdx.x;
    if (i < Nn) { g_deg[i] = 0.0f; g_degin[i] = 0; }
}

__global__ void k_count(const int* __restrict__ ei) {
    int e = blockIdx.x * blockDim.x + threadIdx.x;
    if (e < Ee) {
        atomicAdd(&g_deg[ei[e]], 1.0f);
        atomicAdd(&g_degin[ei[Ee + e]], 1);
    }
}

__global__ void k_scan() {
    __shared__ int part[1024];
    int t = threadIdx.x;
    const int CH = 10;
    int base = t * CH;
    int local[CH];
    int s = 0;
#pragma unroll
    for (int i = 0; i < CH; i++) {
        int idx = base + i;
        int v = (idx < Nn) ? g_degin[idx] : 0;
        local[i] = v; s += v;
    }
    part[t] = s;
    __syncthreads();
    for (int off = 1; off < 1024; off <<= 1) {
        int v = (t >= off) ? part[t - off] : 0;
        __syncthreads();
        part[t] += v;
        __syncthreads();
    }
    int pre = (t == 0) ? 0 : part[t - 1];
#pragma unroll
    for (int i = 0; i < CH; i++) {
        int idx = base + i;
        if (idx < Nn) { g_off[idx] = pre; g_cur[idx] = pre; pre += local[i]; }
    }
    if (t == 1023) g_off[Nn] = part[1023];
}

__global__ void k_fill(const int* __restrict__ ei) {
    int e = blockIdx.x * blockDim.x + threadIdx.x;
    if (e < Ee) {
        int c = ei[Ee + e];
        int p = atomicAdd(&g_cur[c], 1);
        g_srcs[p] = ei[e];
    }
}

// ---------------- Lhat via CSR gather, in x's native (b,n,f,t) layout ----------------
__global__ void k_lhat1(const float* __restrict__ x, const float* __restrict__ lamp) {
    int n = blockIdx.x, j = threadIdx.x;
    int b = j / SEG4, r4 = j - b * SEG4;
    int boff = b * Nn;
    const float4* u = (const float4*)x;
    float4 acc = make_float4(0.f, 0.f, 0.f, 0.f);
    int e = g_off[n], e1 = g_off[n + 1];
    for (; e + 4 <= e1; e += 4) {
        int s0 = g_srcs[e], s1 = g_srcs[e + 1], s2 = g_srcs[e + 2], s3 = g_srcs[e + 3];
        float4 v0 = u[(boff + s0) * SEG4 + r4], v1 = u[(boff + s1) * SEG4 + r4];
        float4 v2 = u[(boff + s2) * SEG4 + r4], v3 = u[(boff + s3) * SEG4 + r4];
        acc.x += (v0.x + v1.x) + (v2.x + v3.x);
        acc.y += (v0.y + v1.y) + (v2.y + v3.y);
        acc.z += (v0.z + v1.z) + (v2.z + v3.z);
        acc.w += (v0.w + v1.w) + (v2.w + v3.w);
    }
    for (; e < e1; e++) {
        float4 v = u[(boff + g_srcs[e]) * SEG4 + r4];
        acc.x += v.x; acc.y += v.y; acc.z += v.z; acc.w += v.w;
    }
    float4 un = u[(boff + n) * SEG4 + r4];
    float c2 = 2.0f / lamp[0];
    float dn = g_deg[n];
    float4 r;
    r.x = c2 * (dn * un.x - acc.x) - un.x;
    r.y = c2 * (dn * un.y - acc.y) - un.y;
    r.z = c2 * (dn * un.z - acc.z) - un.z;
    r.w = c2 * (dn * un.w - acc.w) - un.w;
    ((float4*)g_Tx1)[(boff + n) * SEG4 + r4] = r;
}

__global__ void k_lhat2(const float* __restrict__ x, const float* __restrict__ lamp) {
    int n = blockIdx.x, j = threadIdx.x;
    int b = j / SEG4, r4 = j - b * SEG4;
    int boff = b * Nn;
    const float4* u = (const float4*)g_Tx1;
    float4 acc = make_float4(0.f, 0.f, 0.f, 0.f);
    int e = g_off[n], e1 = g_off[n + 1];
    for (; e + 4 <= e1; e += 4) {
        int s0 = g_srcs[e], s1 = g_srcs[e + 1], s2 = g_srcs[e + 2], s3 = g_srcs[e + 3];
        float4 v0 = u[(boff + s0) * SEG4 + r4], v1 = u[(boff + s1) * SEG4 + r4];
        float4 v2 = u[(boff + s2) * SEG4 + r4], v3 = u[(boff + s3) * SEG4 + r4];
        acc.x += (v0.x + v1.x) + (v2.x + v3.x);
        acc.y += (v0.y + v1.y) + (v2.y + v3.y);
        acc.z += (v0.z + v1.z) + (v2.z + v3.z);
        acc.w += (v0.w + v1.w) + (v2.w + v3.w);
    }
    for (; e < e1; e++) {
        float4 v = u[(boff + g_srcs[e]) * SEG4 + r4];
        acc.x += v.x; acc.y += v.y; acc.z += v.z; acc.w += v.w;
    }
    float4 un = u[(boff + n) * SEG4 + r4];
    float4 t0 = ((const float4*)x)[(boff + n) * SEG4 + r4];
    float c2 = 2.0f / lamp[0];
    float dn = g_deg[n];
    float4 r;
    r.x = 2.0f * (c2 * (dn * un.x - acc.x) - un.x) - t0.x;
    r.y = 2.0f * (c2 * (dn * un.y - acc.y) - un.y) - t0.y;
    r.z = 2.0f * (c2 * (dn * un.z - acc.z) - un.z) - t0.z;
    r.w = 2.0f * (c2 * (dn * un.w - acc.w) - un.w) - t0.w;
    ((float4*)g_Tx2)[(boff + n) * SEG4 + r4] = r;
}

// ---------------- fully-tensor fused kernel, M=48 per node ----------------
// group = one node, 64 threads (2 warps): logical rows r=b*12+t (48 rows =
// exactly 3 m16 tiles, zero M-padding waste). Fragment row mapping
// (b=r/12, t=r%12) is precomputed per thread; weights load once per node.
//
// smem (floats):
//   WF [0,16384)   fragment-ordered split weights (same layout as R7)
//   cb/trb/gma/bta [16384,16640)
// per group (base 16640, stride 8144):
//   A region [0,3712): Ah[4 b][16 t][58] bf16, Am at +1856 floats
//                      (myhs f32[48][64] = 3072 floats overlays this region)
//   Sh +3712 (2072): per-b planes [14 tpos][74] bf16  (rows 0,13 zero-pad)
//   Sm +5784 (2072)
//   ps +7856 (96 = [2 warp][48 row]) pq +7952 (96) mymu +8048 (48) myrs +8096 (48)
#define A_ROW 58
#define A_BSTR 928        // bf16 per b-plane (16*58)
#define S_ROW 74
#define S_BSTR 1036       // bf16 per b-plane (14*74)
#define GB_BASE 16640
#define GB_STRIDE 8144
#define SMEM_FLOATS (GB_BASE + 4 * GB_STRIDE)   // 49216 floats = 196864 B

__global__ void __launch_bounds__(256, 1)
k_fused(const float* __restrict__ x,
        const float* __restrict__ chebW, const float* __restrict__ chebB,
        const float* __restrict__ timeW, const float* __restrict__ timeB,
        const float* __restrict__ resW,  const float* __restrict__ resB,
        const float* __restrict__ gamma, const float* __restrict__ beta,
        float* __restrict__ out)
{
    extern __shared__ float sm[];
    uint32_t* WFu = (uint32_t*)sm;
    float* cb  = sm + 16384;
    float* trb = sm + 16448;
    float* gma = sm + 16512;
    float* bta = sm + 16576;

    int tid = threadIdx.x;

    // --- one-time fragment-ordered weight staging (identical to R7) ---
    for (int e = tid; e < 128 * 32; e += 256) {
        int chunk = e >> 5, ln = e & 31;
        int half = ln >> 2;
        int kp = (ln & 3) * 2;
        float w0, w1, w2, w3;
        if (chunk < 24) {
            int kt = chunk >> 3, nt = chunk & 7;
            int bcol = nt * 8 + half;
            int r = kt * 16 + kp;
            w0 = chebW[r * 64 + bcol];       w1 = chebW[(r + 1) * 64 + bcol];
            w2 = chebW[(r + 8) * 64 + bcol]; w3 = chebW[(r + 9) * 64 + bcol];
        } else if (chunk < 120) {
            int q = chunk - 24;
            int d = q >> 5, kt = (q >> 3) & 3, nt = q & 7;
            int bcol = nt * 8 + half;
            int ci = kt * 16 + kp;
            w0 = timeW[bcol * 192 + ci * 3 + d];
            w1 = timeW[bcol * 192 + (ci + 1) * 3 + d];
            w2 = timeW[bcol * 192 + (ci + 8) * 3 + d];
            w3 = timeW[bcol * 192 + (ci + 9) * 3 + d];
        } else {
            int nt = chunk - 120;
            int bcol = nt * 8 + half;
            w0 = resW[bcol * 16 + kp];     w1 = resW[bcol * 16 + kp + 1];
            w2 = resW[bcol * 16 + kp + 8]; w3 = resW[bcol * 16 + kp + 9];
        }
        float h0 = __bfloat162float(__float2bfloat16(w0));
        float h1 = __bfloat162float(__float2bfloat16(w1));
        float h2 = __bfloat162float(__float2bfloat16(w2));
        float h3 = __bfloat162float(__float2bfloat16(w3));
        uint32_t* p = WFu + chunk * 128 + ln * 4;
        p[0] = pk2(w0, w1);
        p[1] = pk2(w2, w3);
        p[2] = pk2(w0 - h0, w1 - h1);
        p[3] = pk2(w2 - h2, w3 - h3);
    }
    if (tid < 64) {
        cb[tid]  = chebB[tid];
        trb[tid] = timeB[tid] + resB[tid];
        gma[tid] = gamma[tid];
        bta[tid] = beta[tid];
    }

    const int g = tid >> 6;        // group 0..3 (one node each)
    const int c = tid & 63;
    const int lane = tid & 31;
    const int w01 = (tid >> 5) & 1;
    const int gr = lane >> 2;
    const int qk = (lane & 3) * 2;

    float* gbase = sm + GB_BASE + g * GB_STRIDE;
    bf16*  Ah    = (bf16*)gbase;                 // + b*A_BSTR + t*A_ROW
    bf16*  Am    = (bf16*)(gbase + 1856);
    float* myhs  = gbase;                        // overlays A region
    bf16*  Sh    = (bf16*)(gbase + 3712);        // + b*S_BSTR + tpos*S_ROW
    bf16*  Sm    = (bf16*)(gbase + 5784);
    float* ps    = gbase + 7856;                 // [2][48]
    float* pq    = gbase + 7952;
    float* mymu  = gbase + 8048;
    float* myrs  = gbase + 8096;

    // precomputed per-thread fragment row mapping (static across nodes)
    int offA0[3], offA1[3];     // bf16 offsets into A planes for rows r0,r1
    int offS0[3], offS1[3];     // bf16 offsets into S planes (tpos = t, add d*S_ROW)
    int rr0[3], rr1[3];
#pragma unroll
    for (int mt = 0; mt < 3; mt++) {
        int r0 = mt * 16 + gr, r1 = r0 + 8;
        int b0 = r0 / 12, t0 = r0 - b0 * 12;
        int b1 = r1 / 12, t1 = r1 - b1 * 12;
        offA0[mt] = b0 * A_BSTR + t0 * A_ROW;
        offA1[mt] = b1 * A_BSTR + t1 * A_ROW;
        offS0[mt] = b0 * S_BSTR + t0 * S_ROW;
        offS1[mt] = b1 * S_BSTR + t1 * S_ROW;
        rr0[mt] = r0; rr1[mt] = r1;
    }

    // one-time per-group init: S zero-padding rows 0 and 13 (cols 0..63)
    {
        bf16 z = __float2bfloat16(0.f);
#pragma unroll
        for (int b = 0; b < 4; b++) {
            Sh[b * S_BSTR + 0 * S_ROW + c]  = z;
            Sh[b * S_BSTR + 13 * S_ROW + c] = z;
            Sm[b * S_BSTR + 0 * S_ROW + c]  = z;
            Sm[b * S_BSTR + 13 * S_ROW + c] = z;
        }
    }
    __syncthreads();   // weights + inits visible

    for (int n = blockIdx.x * 4 + g; n < Nn; n += 592) {

        // ---- Stage 0: load x/Tx1/Tx2 for all 4 b, build bf16 split A planes ----
        {
            const float* srcs[3] = { x, g_Tx1, g_Tx2 };
#pragma unroll
            for (int kk = 0; kk < 3; kk++) {
#pragma unroll
                for (int b = 0; b < 4; b++) {
                    const float* p = srcs[kk] + (size_t)(b * Nn + n) * SEG;
                    bf16* ah = Ah + b * A_BSTR + kk * 16;
                    bf16* am = Am + b * A_BSTR + kk * 16;
#pragma unroll
                    for (int rep = 0; rep < 3; rep++) {
                        int rr = rep * 64 + c;          // rr = f*12 + t
                        int f = rr / 12, t = rr - f * 12;
                        float v = p[rr];
                        bf16 h = __float2bfloat16(v);
                        ah[t * A_ROW + f] = h;
                        am[t * A_ROW + f] = __float2bfloat16(v - __bfloat162float(h));
                    }
                }
            }
        }
        GROUP_BAR(g);

        // ---- Stage A: cheb projection (M=48) -> relu -> S split planes ----
        {
            float CA[3][4][4];
#pragma unroll
            for (int mt = 0; mt < 3; mt++)
#pragma unroll
                for (int nt = 0; nt < 4; nt++)
#pragma unroll
                    for (int r = 0; r < 4; r++) CA[mt][nt][r] = 0.f;

#pragma unroll
            for (int kt = 0; kt < 3; kt++) {
                int acol = kt * 16 + qk;
                uint32_t ah[3][4], am[3][4];
#pragma unroll
                for (int mt = 0; mt < 3; mt++) {
                    ah[mt][0] = *(const uint32_t*)(Ah + offA0[mt] + acol);
                    ah[mt][1] = *(const uint32_t*)(Ah + offA1[mt] + acol);
                    ah[mt][2] = *(const uint32_t*)(Ah + offA0[mt] + acol + 8);
                    ah[mt][3] = *(const uint32_t*)(Ah + offA1[mt] + acol + 8);
                    am[mt][0] = *(const uint32_t*)(Am + offA0[mt] + acol);
                    am[mt][1] = *(const uint32_t*)(Am + offA1[mt] + acol);
                    am[mt][2] = *(const uint32_t*)(Am + offA0[mt] + acol + 8);
                    am[mt][3] = *(const uint32_t*)(Am + offA1[mt] + acol + 8);
                }
                int cbase = kt * 8 + w01 * 4;
#pragma unroll
                for (int ntl = 0; ntl < 4; ntl++) {
                    uint4 wb = *(const uint4*)(WFu + (cbase + ntl) * 128 + lane * 4);
#pragma unroll
                    for (int mt = 0; mt < 3; mt++) {
                        mma_bf16(CA[mt][ntl], ah[mt], wb.x, wb.y);
                        mma_bf16(CA[mt][ntl], ah[mt], wb.z, wb.w);
                        mma_bf16(CA[mt][ntl], am[mt], wb.x, wb.y);
                    }
                }
            }
            // epilogue: bias+relu -> bf16 split -> S (row tpos = t+1)
#pragma unroll
            for (int mt = 0; mt < 3; mt++) {
#pragma unroll
                for (int ntl = 0; ntl < 4; ntl++) {
                    int ccol = w01 * 32 + ntl * 8 + qk;
                    float b0 = cb[ccol], b1 = cb[ccol + 1];
                    float v0 = fmaxf(CA[mt][ntl][0] + b0, 0.f);
                    float v1 = fmaxf(CA[mt][ntl][1] + b1, 0.f);
                    float h0 = __bfloat162float(__float2bfloat16(v0));
                    float h1 = __bfloat162float(__float2bfloat16(v1));
                    *(uint32_t*)(Sh + offS0[mt] + S_ROW + ccol) = pk2(v0, v1);
                    *(uint32_t*)(Sm + offS0[mt] + S_ROW + ccol) = pk2(v0 - h0, v1 - h1);
                    float v2 = fmaxf(CA[mt][ntl][2] + b0, 0.f);
                    float v3 = fmaxf(CA[mt][ntl][3] + b1, 0.f);
                    float h2 = __bfloat162float(__float2bfloat16(v2));
                    float h3 = __bfloat162float(__float2bfloat16(v3));
                    *(uint32_t*)(Sh + offS1[mt] + S_ROW + ccol) = pk2(v2, v3);
                    *(uint32_t*)(Sm + offS1[mt] + S_ROW + ccol) = pk2(v2 - h2, v3 - h3);
                }
            }
        }
        GROUP_BAR(g);

        // ---- Stage B: conv (3 shifted GEMMs) + residual GEMM ----
        float CB[3][4][4];
#pragma unroll
        for (int mt = 0; mt < 3; mt++)
#pragma unroll
            for (int nt = 0; nt < 4; nt++)
#pragma unroll
                for (int r = 0; r < 4; r++) CB[mt][nt][r] = 0.f;

#pragma unroll
        for (int d = 0; d < 3; d++) {
#pragma unroll
            for (int kt = 0; kt < 4; kt++) {
                int acol = kt * 16 + qk;
                uint32_t ah[3][4], am[3][4];
#pragma unroll
                for (int mt = 0; mt < 3; mt++) {
                    int o0 = offS0[mt] + d * S_ROW;
                    int o1 = offS1[mt] + d * S_ROW;
                    ah[mt][0] = *(const uint32_t*)(Sh + o0 + acol);
                    ah[mt][1] = *(const uint32_t*)(Sh + o1 + acol);
                    ah[mt][2] = *(const uint32_t*)(Sh + o0 + acol + 8);
                    ah[mt][3] = *(const uint32_t*)(Sh + o1 + acol + 8);
                    am[mt][0] = *(const uint32_t*)(Sm + o0 + acol);
                    am[mt][1] = *(const uint32_t*)(Sm + o1 + acol);
                    am[mt][2] = *(const uint32_t*)(Sm + o0 + acol + 8);
                    am[mt][3] = *(const uint32_t*)(Sm + o1 + acol + 8);
                }
                int cbase = 24 + d * 32 + kt * 8 + w01 * 4;
#pragma unroll
                for (int ntl = 0; ntl < 4; ntl++) {
                    uint4 wb = *(const uint4*)(WFu + (cbase + ntl) * 128 + lane * 4);
#pragma unroll
                    for (int mt = 0; mt < 3; mt++) {
                        mma_bf16(CB[mt][ntl], ah[mt], wb.x, wb.y);
                        mma_bf16(CB[mt][ntl], ah[mt], wb.z, wb.w);
                        mma_bf16(CB[mt][ntl], am[mt], wb.x, wb.y);
                    }
                }
            }
        }
        // residual GEMM (K=16, A = x plane = cheb k=0 cols of A planes)
        {
            uint32_t ah[3][4], am[3][4];
#pragma unroll
            for (int mt = 0; mt < 3; mt++) {
                ah[mt][0] = *(const uint32_t*)(Ah + offA0[mt] + qk);
                ah[mt][1] = *(const uint32_t*)(Ah + offA1[mt] + qk);
                ah[mt][2] = *(const uint32_t*)(Ah + offA0[mt] + qk + 8);
                ah[mt][3] = *(const uint32_t*)(Ah + offA1[mt] + qk + 8);
                am[mt][0] = *(const uint32_t*)(Am + offA0[mt] + qk);
                am[mt][1] = *(const uint32_t*)(Am + offA1[mt] + qk);
                am[mt][2] = *(const uint32_t*)(Am + offA0[mt] + qk + 8);
                am[mt][3] = *(const uint32_t*)(Am + offA1[mt] + qk + 8);
            }
            int cbase = 120 + w01 * 4;
#pragma unroll
            for (int ntl = 0; ntl < 4; ntl++) {
                uint4 wb = *(const uint4*)(WFu + (cbase + ntl) * 128 + lane * 4);
#pragma unroll
                for (int mt = 0; mt < 3; mt++) {
                    mma_bf16(CB[mt][ntl], ah[mt], wb.x, wb.y);
                    mma_bf16(CB[mt][ntl], ah[mt], wb.z, wb.w);
                    mma_bf16(CB[mt][ntl], am[mt], wb.x, wb.y);
                }
            }
        }
        GROUP_BAR(g);   // all A-region reads done; safe to overlay with myhs

        // ---- Stage B epilogue: bias+relu -> myhs, plus quad-partial LN stats ----
        {
#pragma unroll
            for (int mt = 0; mt < 3; mt++) {
                float s0 = 0.f, q0 = 0.f, s1 = 0.f, q1 = 0.f;
#pragma unroll
                for (int ntl = 0; ntl < 4; ntl++) {
                    int ccol = w01 * 32 + ntl * 8 + qk;
                    float b0 = trb[ccol], b1 = trb[ccol + 1];
                    float v0 = fmaxf(CB[mt][ntl][0] + b0, 0.f);
                    float v1 = fmaxf(CB[mt][ntl][1] + b1, 0.f);
                    float v2 = fmaxf(CB[mt][ntl][2] + b0, 0.f);
                    float v3 = fmaxf(CB[mt][ntl][3] + b1, 0.f);
                    *(float2*)(myhs + rr0[mt] * 64 + ccol) = make_float2(v0, v1);
                    *(float2*)(myhs + rr1[mt] * 64 + ccol) = make_float2(v2, v3);
                    s0 += v0 + v1; q0 += v0 * v0 + v1 * v1;
                    s1 += v2 + v3; q1 += v2 * v2 + v3 * v3;
                }
                // quad reduction over the 4 lanes covering this warp's 32 cols
                s0 += __shfl_xor_sync(0xffffffffu, s0, 1);
                s0 += __shfl_xor_sync(0xffffffffu, s0, 2);
                q0 += __shfl_xor_sync(0xffffffffu, q0, 1);
                q0 += __shfl_xor_sync(0xffffffffu, q0, 2);
                s1 += __shfl_xor_sync(0xffffffffu, s1, 1);
                s1 += __shfl_xor_sync(0xffffffffu, s1, 2);
                q1 += __shfl_xor_sync(0xffffffffu, q1, 1);
                q1 += __shfl_xor_sync(0xffffffffu, q1, 2);
                if ((lane & 3) == 0) {
                    ps[w01 * 48 + rr0[mt]] = s0;
                    pq[w01 * 48 + rr0[mt]] = q0;
                    ps[w01 * 48 + rr1[mt]] = s1;
                    pq[w01 * 48 + rr1[mt]] = q1;
                }
            }
        }
        GROUP_BAR(g);

        // ---- LN stats combine (48 rows) ----
        if (c < 48) {
            float s = ps[c] + ps[48 + c];
            float q2 = pq[c] + pq[48 + c];
            float mu = s * (1.0f / 64.0f);
            float var = q2 * (1.0f / 64.0f) - mu * mu;
            mymu[c] = mu;
            myrs[c] = rsqrtf(var + 1e-5f);
        }
        GROUP_BAR(g);

        // ---- normalize + write out (B,N,C,T) ----
        {
            float ga = gma[c], be = bta[c];
#pragma unroll
            for (int b = 0; b < 4; b++) {
                float o[12];
#pragma unroll
                for (int t = 0; t < 12; t++) {
                    int r = b * 12 + t;
                    o[t] = (myhs[r * 64 + c] - mymu[r]) * myrs[r] * ga + be;
                }
                float* op = out + (((size_t)b * Nn + n) * 64 + c) * 12;
                float4* op4 = (float4*)op;
                op4[0] = make_float4(o[0], o[1], o[2],  o[3]);
                op4[1] = make_float4(o[4], o[5], o[6],  o[7]);
                op4[2] = make_float4(o[8], o[9], o[10], o[11]);
            }
        }
        GROUP_BAR(g);   // myhs reads done before next tile's stage-0 A writes
    }
}

// ---------------- launcher ----------------
extern "C" void kernel_launch(void* const* d_in, const int* in_sizes, int n_in,
                              void* d_out, int out_size)
{
    const float* x     = (const float*)d_in[0];
    const int*   ei    = (const int*)d_in[1];
    const float* lam   = (const float*)d_in[2];
    const float* chebW = (const float*)d_in[3];
    const float* chebB = (const float*)d_in[4];
    const float* timeW = (const float*)d_in[5];
    const float* timeB = (const float*)d_in[6];
    const float* resW  = (const float*)d_in[7];
    const float* resB  = (const float*)d_in[8];
    const float* gma   = (const float*)d_in[9];
    const float* bta   = (const float*)d_in[10];
    float* out = (float*)d_out;

    k_zero<<<(Nn + 255) / 256, 256>>>();
    k_count<<<(Ee + 255) / 256, 256>>>(ei);
    k_scan<<<1, 1024>>>();
    k_fill<<<(Ee + 255) / 256, 256>>>(ei);
    k_lhat1<<<Nn, 192>>>(x, lam);
    k_lhat2<<<Nn, 192>>>(x, lam);

    cudaFuncSetAttribute(k_fused, cudaFuncAttributeMaxDynamicSharedMemorySize,
                         SMEM_FLOATS * 4);
    // 148 blocks x 256 threads: 1 block/SM, 4 node-groups per block
    k_fused<<<148, 256, SMEM_FLOATS * 4>>>(x, chebW, chebB, timeW, timeB,
                                           resW, resB, gma, bta, out);
}

// round 9
// speedup vs baseline: 2.6468x; 1.1424x over previous
#include <cuda_runtime.h>
#include <cuda_bf16.h>
#include <cstdint>

// Problem constants
#define Nn   10000
#define Bb   4
#define Ff   16
#define Tt   12
#define Ee   160000
#define Cc   64
#define SEG  192          // floats per (n,b) row (f*12+t)
#define SEG4 48           // float4 per (n,b) row

typedef unsigned long long u64;

#define GROUP_BAR(gid) asm volatile("bar.sync %0, 64;" :: "r"((gid) + 1) : "memory")

__device__ __forceinline__ void mma_tf32(float c[4], const uint32_t a[4],
                                         uint32_t b0, uint32_t b1) {
    asm volatile(
        "mma.sync.aligned.m16n8k8.row.col.f32.tf32.tf32.f32 "
        "{%0,%1,%2,%3}, {%4,%5,%6,%7}, {%8,%9}, {%0,%1,%2,%3};"
        : "+f"(c[0]), "+f"(c[1]), "+f"(c[2]), "+f"(c[3])
        : "r"(a[0]), "r"(a[1]), "r"(a[2]), "r"(a[3]), "r"(b0), "r"(b1));
}

__device__ __forceinline__ uint32_t tf32u(float x) {
    uint32_t r;
    asm("cvt.rna.tf32.f32 %0, %1;" : "=r"(r) : "f"(x));
    return r;
}
__device__ __forceinline__ uint32_t ldsm32(const float* p) {
    return *reinterpret_cast<const uint32_t*>(p);
}

// ---------------- scratch (device globals; no allocation) ----------------
__device__ float g_Tx1[Nn * Bb * SEG];
__device__ float g_Tx2[Nn * Bb * SEG];
__device__ float g_deg[Nn];
__device__ int   g_degin[Nn];
__device__ int   g_off[Nn + 1];
__device__ int   g_cur[Nn];
__device__ int   g_srcs[Ee];

// ---------------- graph preprocessing ----------------
__global__ void k_zero() {
    int i = blockIdx.x * blockDim.x + threadIdx.x;
    if (i < Nn) { g_deg[i] = 0.0f; g_degin[i] = 0; }
}

__global__ void k_count(const int* __restrict__ ei) {
    int e = blockIdx.x * blockDim.x + threadIdx.x;
    if (e < Ee) {
        atomicAdd(&g_deg[ei[e]], 1.0f);
        atomicAdd(&g_degin[ei[Ee + e]], 1);
    }
}

__global__ void k_scan() {
    __shared__ int part[1024];
    int t = threadIdx.x;
    const int CH = 10;
    int base = t * CH;
    int local[CH];
    int s = 0;
#pragma unroll
    for (int i = 0; i < CH; i++) {
        int idx = base + i;
        int v = (idx < Nn) ? g_degin[idx] : 0;
        local[i] = v; s += v;
    }
    part[t] = s;
    __syncthreads();
    for (int off = 1; off < 1024; off <<= 1) {
        int v = (t >= off) ? part[t - off] : 0;
        __syncthreads();
        part[t] += v;
        __syncthreads();
    }
    int pre = (t == 0) ? 0 : part[t - 1];
#pragma unroll
    for (int i = 0; i < CH; i++) {
        int idx = base + i;
        if (idx < Nn) { g_off[idx] = pre; g_cur[idx] = pre; pre += local[i]; }
    }
    if (t == 1023) g_off[Nn] = part[1023];
}

__global__ void k_fill(const int* __restrict__ ei) {
    int e = blockIdx.x * blockDim.x + threadIdx.x;
    if (e < Ee) {
        int c = ei[Ee + e];
        int p = atomicAdd(&g_cur[c], 1);
        g_srcs[p] = ei[e];
    }
}

// ---------------- Lhat via CSR gather, in x's native (b,n,f,t) layout ----------------
__global__ void k_lhat1(const float* __restrict__ x, const float* __restrict__ lamp) {
    int n = blockIdx.x, j = threadIdx.x;
    int b = j / SEG4, r4 = j - b * SEG4;
    int boff = b * Nn;
    const float4* u = (const float4*)x;
    float4 acc = make_float4(0.f, 0.f, 0.f, 0.f);
    int e = g_off[n], e1 = g_off[n + 1];
    for (; e + 4 <= e1; e += 4) {
        int s0 = g_srcs[e], s1 = g_srcs[e + 1], s2 = g_srcs[e + 2], s3 = g_srcs[e + 3];
        float4 v0 = u[(boff + s0) * SEG4 + r4], v1 = u[(boff + s1) * SEG4 + r4];
        float4 v2 = u[(boff + s2) * SEG4 + r4], v3 = u[(boff + s3) * SEG4 + r4];
        acc.x += (v0.x + v1.x) + (v2.x + v3.x);
        acc.y += (v0.y + v1.y) + (v2.y + v3.y);
        acc.z += (v0.z + v1.z) + (v2.z + v3.z);
        acc.w += (v0.w + v1.w) + (v2.w + v3.w);
    }
    for (; e < e1; e++) {
        float4 v = u[(boff + g_srcs[e]) * SEG4 + r4];
        acc.x += v.x; acc.y += v.y; acc.z += v.z; acc.w += v.w;
    }
    float4 un = u[(boff + n) * SEG4 + r4];
    float c2 = 2.0f / lamp[0];
    float dn = g_deg[n];
    float4 r;
    r.x = c2 * (dn * un.x - acc.x) - un.x;
    r.y = c2 * (dn * un.y - acc.y) - un.y;
    r.z = c2 * (dn * un.z - acc.z) - un.z;
    r.w = c2 * (dn * un.w - acc.w) - un.w;
    ((float4*)g_Tx1)[(boff + n) * SEG4 + r4] = r;
}

__global__ void k_lhat2(const float* __restrict__ x, const float* __restrict__ lamp) {
    int n = blockIdx.x, j = threadIdx.x;
    int b = j / SEG4, r4 = j - b * SEG4;
    int boff = b * Nn;
    const float4* u = (const float4*)g_Tx1;
    float4 acc = make_float4(0.f, 0.f, 0.f, 0.f);
    int e = g_off[n], e1 = g_off[n + 1];
    for (; e + 4 <= e1; e += 4) {
        int s0 = g_srcs[e], s1 = g_srcs[e + 1], s2 = g_srcs[e + 2], s3 = g_srcs[e + 3];
        float4 v0 = u[(boff + s0) * SEG4 + r4], v1 = u[(boff + s1) * SEG4 + r4];
        float4 v2 = u[(boff + s2) * SEG4 + r4], v3 = u[(boff + s3) * SEG4 + r4];
        acc.x += (v0.x + v1.x) + (v2.x + v3.x);
        acc.y += (v0.y + v1.y) + (v2.y + v3.y);
        acc.z += (v0.z + v1.z) + (v2.z + v3.z);
        acc.w += (v0.w + v1.w) + (v2.w + v3.w);
    }
    for (; e < e1; e++) {
        float4 v = u[(boff + g_srcs[e]) * SEG4 + r4];
        acc.x += v.x; acc.y += v.y; acc.z += v.z; acc.w += v.w;
    }
    float4 un = u[(boff + n) * SEG4 + r4];
    float4 t0 = ((const float4*)x)[(boff + n) * SEG4 + r4];
    float c2 = 2.0f / lamp[0];
    float dn = g_deg[n];
    float4 r;
    r.x = 2.0f * (c2 * (dn * un.x - acc.x) - un.x) - t0.x;
    r.y = 2.0f * (c2 * (dn * un.y - acc.y) - un.y) - t0.y;
    r.z = 2.0f * (c2 * (dn * un.z - acc.z) - un.z) - t0.z;
    r.w = 2.0f * (c2 * (dn * un.w - acc.w) - un.w) - t0.w;
    ((float4*)g_Tx2)[(boff + n) * SEG4 + r4] = r;
}

// ---------------- fully-tensor fused kernel, TF32, M=48 per node ----------------
// group = one node, 64 threads (2 warps). All GEMMs via mma.m16n8k8.tf32 with
// explicit cvt.rna (unbiased): single-plane A/S operands — no bf16 split.
//
// smem (floats):
//   WF [0,16384)   fragment-ordered tf32 weights: 128 chunks x 32 lanes x uint4
//                  chunk = pair-of-ktiles x ntile; lane holds {b0,b1} of kt even
//                  in .x/.y and of kt odd in .z/.w
//   cb/trb/gma/bta [16384,16640)
// per group (base 16640, stride 7168):
//   A  [0,2496): fp32(tf32) [4 b][12 t][52] (cols j=kk*16+f; kk=0 plane = x)
//   myhs f32[48][64] = 3072 overlays [0,3072)
//   S  [3072,6880): fp32(tf32) [4 b][14 tpos][68] (rows 0,13 zero-pad)
//   ps +6880(96) pq +6976(96) mymu +7072(48) myrs +7120(48)
#define A_ROWF 52
#define A_BSTR 624        // 12*52
#define S_ROWF 68
#define S_BSTR 952        // 14*68
#define GB_BASE 16640
#define GB_STRIDE 7168
#define SMEM_FLOATS (GB_BASE + 4 * GB_STRIDE)   // 45312 floats = 181248 B

__global__ void __launch_bounds__(256, 1)
k_fused(const float* __restrict__ x,
        const float* __restrict__ chebW, const float* __restrict__ chebB,
        const float* __restrict__ timeW, const float* __restrict__ timeB,
        const float* __restrict__ resW,  const float* __restrict__ resB,
        const float* __restrict__ gamma, const float* __restrict__ beta,
        float* __restrict__ out)
{
    extern __shared__ float sm[];
    uint32_t* WFu = (uint32_t*)sm;
    const uint4* WF4 = (const uint4*)sm;
    float* cb  = sm + 16384;
    float* trb = sm + 16448;
    float* gma = sm + 16512;
    float* bta = sm + 16576;

    int tid = threadIdx.x;

    // --- one-time fragment-ordered tf32 weight staging ---
    for (int e = tid; e < 128 * 32; e += 256) {
        int chunk = e >> 5, ln = e & 31;
        int krow = ln & 3;
        int nh = ln >> 2;
        float w0, w1, w2, w3;
        if (chunk < 24) {              // cheb: K=48, pairs p=0..2, nt 0..7
            int p = chunk >> 3, nt = chunk & 7;
            int n = nt * 8 + nh;
            int k0 = p * 16 + krow;
            w0 = chebW[k0 * 64 + n];        w1 = chebW[(k0 + 4) * 64 + n];
            w2 = chebW[(k0 + 8) * 64 + n];  w3 = chebW[(k0 + 12) * 64 + n];
        } else if (chunk < 120) {      // conv: d(3) x pairs(4) x nt(8)
            int q = chunk - 24;
            int d = q >> 5, p = (q >> 3) & 3, nt = q & 7;
            int n = nt * 8 + nh;
            int ci0 = p * 16 + krow;
            w0 = timeW[n * 192 + ci0 * 3 + d];
            w1 = timeW[n * 192 + (ci0 + 4) * 3 + d];
            w2 = timeW[n * 192 + (ci0 + 8) * 3 + d];
            w3 = timeW[n * 192 + (ci0 + 12) * 3 + d];
        } else {                       // residual: K=16, 1 pair
            int nt = chunk - 120;
            int n = nt * 8 + nh;
            w0 = resW[n * 16 + krow];      w1 = resW[n * 16 + krow + 4];
            w2 = resW[n * 16 + krow + 8];  w3 = resW[n * 16 + krow + 12];
        }
        uint32_t* p = WFu + chunk * 128 + ln * 4;
        p[0] = tf32u(w0); p[1] = tf32u(w1); p[2] = tf32u(w2); p[3] = tf32u(w3);
    }
    if (tid < 64) {
        cb[tid]  = chebB[tid];
        trb[tid] = timeB[tid] + resB[tid];
        gma[tid] = gamma[tid];
        bta[tid] = beta[tid];
    }

    const int g = tid >> 6;        // group 0..3 (one node each)
    const int c = tid & 63;
    const int lane = tid & 31;
    const int w01 = (tid >> 5) & 1;
    const int gr = lane >> 2;      // fragment row group
    const int kq = lane & 3;       // fragment k/col index

    float* gbase = sm + GB_BASE + g * GB_STRIDE;
    float* Af    = gbase;                 // A planes (2496) -- myhs overlays
    float* myhs  = gbase;                 // f32[48][64]
    float* Sf    = gbase + 3072;          // S planes (3808)
    float* ps    = gbase + 6880;
    float* pq    = gbase + 6976;
    float* mymu  = gbase + 7072;
    float* myrs  = gbase + 7120;

    // precomputed per-thread fragment row mapping
    int offA0[3], offA1[3], offS0[3], offS1[3], rr0[3], rr1[3];
#pragma unroll
    for (int mt = 0; mt < 3; mt++) {
        int r0 = mt * 16 + gr, r1 = r0 + 8;
        int b0 = r0 / 12, t0 = r0 - b0 * 12;
        int b1 = r1 / 12, t1 = r1 - b1 * 12;
        offA0[mt] = b0 * A_BSTR + t0 * A_ROWF;
        offA1[mt] = b1 * A_BSTR + t1 * A_ROWF;
        offS0[mt] = b0 * S_BSTR + t0 * S_ROWF;
        offS1[mt] = b1 * S_BSTR + t1 * S_ROWF;
        rr0[mt] = r0; rr1[mt] = r1;
    }

    // one-time per-group init: S zero-pad rows 0 and 13 per b-plane
    {
#pragma unroll
        for (int b = 0; b < 4; b++) {
            Sf[b * S_BSTR + 0 * S_ROWF + c]  = 0.f;
            Sf[b * S_BSTR + 13 * S_ROWF + c] = 0.f;
        }
    }
    __syncthreads();

    for (int n = blockIdx.x * 4 + g; n < Nn; n += 592) {

        // ---- Stage 0: vectorized loads of x/Tx1/Tx2 -> tf32 A planes ----
        {
            const float* srcs[3] = { x, g_Tx1, g_Tx2 };
#pragma unroll
            for (int rep = 0; rep < 9; rep++) {
                int i = rep * 64 + c;           // 0..575
                int kkb = i / 48, j = i - kkb * 48;
                int kk = kkb >> 2, b = kkb & 3;
                int f = j / 3, t0 = (j - f * 3) * 4;
                const float4* src4 = (const float4*)
                    (srcs[kk] + (size_t)(b * Nn + n) * SEG);
                float4 v = src4[j];
                float* dst = Af + b * A_BSTR + t0 * A_ROWF + kk * 16 + f;
                dst[0]          = __uint_as_float(tf32u(v.x));
                dst[A_ROWF]     = __uint_as_float(tf32u(v.y));
                dst[2 * A_ROWF] = __uint_as_float(tf32u(v.z));
                dst[3 * A_ROWF] = __uint_as_float(tf32u(v.w));
            }
        }
        GROUP_BAR(g);

        // ---- Stage A: cheb projection (M=48, K=48) -> relu -> S ----
        {
            float CA[3][4][4];
#pragma unroll
            for (int mt = 0; mt < 3; mt++)
#pragma unroll
                for (int nt = 0; nt < 4; nt++)
#pragma unroll
                    for (int r = 0; r < 4; r++) CA[mt][nt][r] = 0.f;

#pragma unroll
            for (int p = 0; p < 3; p++) {
                uint32_t aA[2][3][4];
#pragma unroll
                for (int h = 0; h < 2; h++) {
                    int kcol = (2 * p + h) * 8 + kq;
#pragma unroll
                    for (int mt = 0; mt < 3; mt++) {
                        aA[h][mt][0] = ldsm32(Af + offA0[mt] + kcol);
                        aA[h][mt][1] = ldsm32(Af + offA1[mt] + kcol);
                        aA[h][mt][2] = ldsm32(Af + offA0[mt] + kcol + 4);
                        aA[h][mt][3] = ldsm32(Af + offA1[mt] + kcol + 4);
                    }
                }
#pragma unroll
                for (int ntl = 0; ntl < 4; ntl++) {
                    uint4 wb = WF4[(p * 8 + w01 * 4 + ntl) * 32 + lane];
#pragma unroll
                    for (int mt = 0; mt < 3; mt++) {
                        mma_tf32(CA[mt][ntl], aA[0][mt], wb.x, wb.y);
                        mma_tf32(CA[mt][ntl], aA[1][mt], wb.z, wb.w);
                    }
                }
            }
            // epilogue: bias + relu -> tf32 -> S at tpos = t+1
#pragma unroll
            for (int mt = 0; mt < 3; mt++) {
#pragma unroll
                for (int ntl = 0; ntl < 4; ntl++) {
                    int ccol = w01 * 32 + ntl * 8 + kq * 2;
                    float b0 = cb[ccol], b1 = cb[ccol + 1];
                    Sf[offS0[mt] + S_ROWF + ccol] =
                        __uint_as_float(tf32u(fmaxf(CA[mt][ntl][0] + b0, 0.f)));
                    Sf[offS0[mt] + S_ROWF + ccol + 1] =
                        __uint_as_float(tf32u(fmaxf(CA[mt][ntl][1] + b1, 0.f)));
                    Sf[offS1[mt] + S_ROWF + ccol] =
                        __uint_as_float(tf32u(fmaxf(CA[mt][ntl][2] + b0, 0.f)));
                    Sf[offS1[mt] + S_ROWF + ccol + 1] =
                        __uint_as_float(tf32u(fmaxf(CA[mt][ntl][3] + b1, 0.f)));
                }
            }
        }
        GROUP_BAR(g);

        // ---- Stage B: conv (3 shifted GEMMs, K=64 each) + residual (K=16) ----
        float CB[3][4][4];
#pragma unroll
        for (int mt = 0; mt < 3; mt++)
#pragma unroll
            for (int nt = 0; nt < 4; nt++)
#pragma unroll
                for (int r = 0; r < 4; r++) CB[mt][nt][r] = 0.f;

#pragma unroll
        for (int d = 0; d < 3; d++) {
#pragma unroll
            for (int p = 0; p < 4; p++) {
                uint32_t aS[2][3][4];
#pragma unroll
                for (int h = 0; h < 2; h++) {
                    int kcol = (2 * p + h) * 8 + kq;
#pragma unroll
                    for (int mt = 0; mt < 3; mt++) {
                        int o0 = offS0[mt] + d * S_ROWF;
                        int o1 = offS1[mt] + d * S_ROWF;
                        aS[h][mt][0] = ldsm32(Sf + o0 + kcol);
                        aS[h][mt][1] = ldsm32(Sf + o1 + kcol);
                        aS[h][mt][2] = ldsm32(Sf + o0 + kcol + 4);
                        aS[h][mt][3] = ldsm32(Sf + o1 + kcol + 4);
                    }
                }
#pragma unroll
                for (int ntl = 0; ntl < 4; ntl++) {
                    uint4 wb = WF4[(24 + d * 32 + p * 8 + w01 * 4 + ntl) * 32 + lane];
#pragma unroll
                    for (int mt = 0; mt < 3; mt++) {
                        mma_tf32(CB[mt][ntl], aS[0][mt], wb.x, wb.y);
                        mma_tf32(CB[mt][ntl], aS[1][mt], wb.z, wb.w);
                    }
                }
            }
        }
        // residual GEMM: A = x plane (A cols 0..15)
        {
            uint32_t aR[2][3][4];
#pragma unroll
            for (int h = 0; h < 2; h++) {
                int kcol = h * 8 + kq;
#pragma unroll
                for (int mt = 0; mt < 3; mt++) {
                    aR[h][mt][0] = ldsm32(Af + offA0[mt] + kcol);
                    aR[h][mt][1] = ldsm32(Af + offA1[mt] + kcol);
                    aR[h][mt][2] = ldsm32(Af + offA0[mt] + kcol + 4);
                    aR[h][mt][3] = ldsm32(Af + offA1[mt] + kcol + 4);
                }
            }
#pragma unroll
            for (int ntl = 0; ntl < 4; ntl++) {
                uint4 wb = WF4[(120 + w01 * 4 + ntl) * 32 + lane];
#pragma unroll
                for (int mt = 0; mt < 3; mt++) {
                    mma_tf32(CB[mt][ntl], aR[0][mt], wb.x, wb.y);
                    mma_tf32(CB[mt][ntl], aR[1][mt], wb.z, wb.w);
                }
            }
        }
        GROUP_BAR(g);   // A-region reads done; safe to overlay with myhs

        // ---- Stage B epilogue: bias+relu -> myhs + quad-partial LN stats ----
        {
#pragma unroll
            for (int mt = 0; mt < 3; mt++) {
                float s0 = 0.f, q0 = 0.f, s1 = 0.f, q1 = 0.f;
#pragma unroll
                for (int ntl = 0; ntl < 4; ntl++) {
                    int ccol = w01 * 32 + ntl * 8 + kq * 2;
                    float b0 = trb[ccol], b1 = trb[ccol + 1];
                    float v0 = fmaxf(CB[mt][ntl][0] + b0, 0.f);
                    float v1 = fmaxf(CB[mt][ntl][1] + b1, 0.f);
                    float v2 = fmaxf(CB[mt][ntl][2] + b0, 0.f);
                    float v3 = fmaxf(CB[mt][ntl][3] + b1, 0.f);
                    *(float2*)(myhs + rr0[mt] * 64 + ccol) = make_float2(v0, v1);
                    *(float2*)(myhs + rr1[mt] * 64 + ccol) = make_float2(v2, v3);
                    s0 += v0 + v1; q0 += v0 * v0 + v1 * v1;
                    s1 += v2 + v3; q1 += v2 * v2 + v3 * v3;
                }
                s0 += __shfl_xor_sync(0xffffffffu, s0, 1);
                s0 += __shfl_xor_sync(0xffffffffu, s0, 2);
                q0 += __shfl_xor_sync(0xffffffffu, q0, 1);
                q0 += __shfl_xor_sync(0xffffffffu, q0, 2);
                s1 += __shfl_xor_sync(0xffffffffu, s1, 1);
                s1 += __shfl_xor_sync(0xffffffffu, s1, 2);
                q1 += __shfl_xor_sync(0xffffffffu, q1, 1);
                q1 += __shfl_xor_sync(0xffffffffu, q1, 2);
                if (kq == 0) {
                    ps[w01 * 48 + rr0[mt]] = s0;
                    pq[w01 * 48 + rr0[mt]] = q0;
                    ps[w01 * 48 + rr1[mt]] = s1;
                    pq[w01 * 48 + rr1[mt]] = q1;
                }
            }
        }
        GROUP_BAR(g);

        // ---- LN stats combine (48 rows) ----
        if (c < 48) {
            float s = ps[c] + ps[48 + c];
            float q2 = pq[c] + pq[48 + c];
            float mu = s * (1.0f / 64.0f);
            float var = q2 * (1.0f / 64.0f) - mu * mu;
            mymu[c] = mu;
            myrs[c] = rsqrtf(var + 1e-5f);
        }
        GROUP_BAR(g);

        // ---- normalize + write out (B,N,C,T) ----
        {
            float ga = gma[c], be = bta[c];
#pragma unroll
            for (int b = 0; b < 4; b++) {
                float o[12];
#pragma unroll
                for (int t = 0; t < 12; t++) {
                    int r = b * 12 + t;
                    o[t] = (myhs[r * 64 + c] - mymu[r]) * myrs[r] * ga + be;
                }
                float* op = out + (((size_t)b * Nn + n) * 64 + c) * 12;
                float4* op4 = (float4*)op;
                op4[0] = make_float4(o[0], o[1], o[2],  o[3]);
                op4[1] = make_float4(o[4], o[5], o[6],  o[7]);
                op4[2] = make_float4(o[8], o[9], o[10], o[11]);
            }
        }
        GROUP_BAR(g);   // myhs reads done before next tile's stage-0 A writes
    }
}

// ---------------- launcher ----------------
extern "C" void kernel_launch(void* const* d_in, const int* in_sizes, int n_in,
                              void* d_out, int out_size)
{
    const float* x     = (const float*)d_in[0];
    const int*   ei    = (const int*)d_in[1];
    const float* lam   = (const float*)d_in[2];
    const float* chebW = (const float*)d_in[3];
    const float* chebB = (const float*)d_in[4];
    const float* timeW = (const float*)d_in[5];
    const float* timeB = (const float*)d_in[6];
    const float* resW  = (const float*)d_in[7];
    const float* resB  = (const float*)d_in[8];
    const float* gma   = (const float*)d_in[9];
    const float* bta   = (const float*)d_in[10];
    float* out = (float*)d_out;

    k_zero<<<(Nn + 255) / 256, 256>>>();
    k_count<<<(Ee + 255) / 256, 256>>>(ei);
    k_scan<<<1, 1024>>>();
    k_fill<<<(Ee + 255) / 256, 256>>>(ei);
    k_lhat1<<<Nn, 192>>>(x, lam);
    k_lhat2<<<Nn, 192>>>(x, lam);

    cudaFuncSetAttribute(k_fused, cudaFuncAttributeMaxDynamicSharedMemorySize,
                         SMEM_FLOATS * 4);
    // 148 blocks x 256 threads: 1 block/SM, 4 node-groups per block
    k_fused<<<148, 256, SMEM_FLOATS * 4>>>(x, chebW, chebB, timeW, timeB,
                                           resW, resB, gma, bta, out);
}